// round 14
// baseline (speedup 1.0000x reference)
#include <cuda_runtime.h>
#include <cuda_bf16.h>
#include <math.h>
#include <stdint.h>

#define H 2048
#define S 32
#define NHEAD 8
#define DHD 256
#define NLAYER 3

// ---------------- scratch (device globals; no allocation allowed) ------------
__device__ float g_x[S * H];
__device__ float g_qkv[S * 3 * H];
__device__ float g_part[4194304];
__device__ float g_v1[NLAYER * H];
__device__ float g_v2[NLAYER * H];
__device__ float g_h[1024];
__device__ __nv_bfloat16 g_xh[S * H];
__device__ __nv_bfloat16 g_xl[S * H];
__device__ __nv_bfloat16 g_ah[S * H];
__device__ __nv_bfloat16 g_al[S * H];
__device__ __nv_bfloat16 g_gh[S * 4 * H];
__device__ __nv_bfloat16 g_gl[S * 4 * H];

__device__ __forceinline__ float gelu_f(float v) {
    return 0.5f * v * (1.0f + erff(v * 0.70710678118654752f));
}
__device__ __forceinline__ void split2(float x, __nv_bfloat16& h, __nv_bfloat16& l) {
    unsigned u = __float_as_uint(x);
    h = __ushort_as_bfloat16((unsigned short)(u >> 16));
    l = __float2bfloat16(x - __uint_as_float(u & 0xFFFF0000u));
}

// ---------------- L2 prefetch (hint-only; warms next weight matrix) ----------
__global__ void prefetch_l2(const float* __restrict__ p, int nfloat)
{
    size_t idx = (size_t)blockIdx.x * blockDim.x + threadIdx.x;
    size_t stride = (size_t)gridDim.x * blockDim.x * 32;
    for (size_t i = idx * 32; i < (size_t)nfloat; i += stride)
        asm volatile("prefetch.global.L2 [%0];" :: "l"(p + i));
}

// ======================= HMMA GEMM (R11 version — best passing) ==============
// Cp[32,N] slice = X[32,Kslice] @ W[N,Kslice]^T as D[64 wrow, 32 tok] per block.
// 128 threads / 4 warps. fp32 emulated by bf16 hi/lo split: hh+hl+lh passes.
// 2-deep register pipeline, single smem buffer.

#define WSTR 40   // padded row stride (bf16): 80B; 16B-aligned rows, 0-conflict

__device__ __forceinline__ uint32_t sptr(const void* p) {
    return (uint32_t)__cvta_generic_to_shared(p);
}
__device__ __forceinline__ void ldsm4(uint32_t* r, uint32_t a) {
    asm volatile("ldmatrix.sync.aligned.m8n8.x4.shared.b16 {%0,%1,%2,%3}, [%4];"
                 : "=r"(r[0]), "=r"(r[1]), "=r"(r[2]), "=r"(r[3]) : "r"(a));
}
__device__ __forceinline__ void mma16816(float* d, const uint32_t* a,
                                         uint32_t b0, uint32_t b1) {
    asm volatile(
        "mma.sync.aligned.m16n8k16.row.col.f32.bf16.bf16.f32 "
        "{%0,%1,%2,%3}, {%4,%5,%6,%7}, {%8,%9}, {%0,%1,%2,%3};"
        : "+f"(d[0]), "+f"(d[1]), "+f"(d[2]), "+f"(d[3])
        : "r"(a[0]), "r"(a[1]), "r"(a[2]), "r"(a[3]), "r"(b0), "r"(b1));
}

// stage one 32-k tile from registers into smem (W f32 -> bf16 hi/lo)
__device__ __forceinline__ void gm_stage(
    const float4* wreg, uint4 xh4, uint4 xl4,
    __nv_bfloat16* sWH, __nv_bfloat16* sWL,
    __nv_bfloat16* sXH, __nv_bfloat16* sXL,
    int wrow, int hf, int xrow, int xc)
{
#pragma unroll
    for (int i = 0; i < 4; i++) {
        float4 f = wreg[i];
        unsigned u0 = __float_as_uint(f.x), u1 = __float_as_uint(f.y);
        unsigned u2 = __float_as_uint(f.z), u3 = __float_as_uint(f.w);
        unsigned h01 = __byte_perm(u0, u1, 0x7632);
        unsigned h23 = __byte_perm(u2, u3, 0x7632);
        float l0 = f.x - __uint_as_float(u0 & 0xFFFF0000u);
        float l1 = f.y - __uint_as_float(u1 & 0xFFFF0000u);
        float l2 = f.z - __uint_as_float(u2 & 0xFFFF0000u);
        float l3 = f.w - __uint_as_float(u3 & 0xFFFF0000u);
        unsigned l01, l23;
        asm("cvt.rn.bf16x2.f32 %0, %1, %2;" : "=r"(l01) : "f"(l1), "f"(l0));
        asm("cvt.rn.bf16x2.f32 %0, %1, %2;" : "=r"(l23) : "f"(l3), "f"(l2));
        int e = wrow * WSTR + hf * 16 + i * 4;
        *(uint2*)&sWH[e] = make_uint2(h01, h23);
        *(uint2*)&sWL[e] = make_uint2(l01, l23);
    }
    int e = xrow * WSTR + xc;
    *(uint4*)&sXH[e] = xh4;
    *(uint4*)&sXL[e] = xl4;
}

// consume the staged tile: per warp 16 W-rows, 2 k-steps x (6 ldsm + 12 mma)
__device__ __forceinline__ void gm_compute(
    float acc[4][4],
    const __nv_bfloat16* sWH, const __nv_bfloat16* sWL,
    const __nv_bfloat16* sXH, const __nv_bfloat16* sXL,
    int wid, int lane)
{
    const int m0 = wid * 16;
#pragma unroll
    for (int s = 0; s < 2; s++) {
        uint32_t ah[4], al[4], b0h[4], b1h[4], b0l[4], b1l[4];
        {
            int arow = m0 + (lane & 15);
            int acol = s * 16 + ((lane >> 4) << 3);
            ldsm4(ah, sptr(&sWH[arow * WSTR + acol]));
            ldsm4(al, sptr(&sWL[arow * WSTR + acol]));
        }
        {
            int brow = ((lane >> 4) << 3) + (lane & 7);
            int bcol = s * 16 + (lane & 8);
            ldsm4(b0h, sptr(&sXH[brow * WSTR + bcol]));
            ldsm4(b1h, sptr(&sXH[(16 + brow) * WSTR + bcol]));
            ldsm4(b0l, sptr(&sXL[brow * WSTR + bcol]));
            ldsm4(b1l, sptr(&sXL[(16 + brow) * WSTR + bcol]));
        }
        // hh
        mma16816(acc[0], ah, b0h[0], b0h[1]);
        mma16816(acc[1], ah, b0h[2], b0h[3]);
        mma16816(acc[2], ah, b1h[0], b1h[1]);
        mma16816(acc[3], ah, b1h[2], b1h[3]);
        // hl
        mma16816(acc[0], ah, b0l[0], b0l[1]);
        mma16816(acc[1], ah, b0l[2], b0l[3]);
        mma16816(acc[2], ah, b1l[0], b1l[1]);
        mma16816(acc[3], ah, b1l[2], b1l[3]);
        // lh
        mma16816(acc[0], al, b0h[0], b0h[1]);
        mma16816(acc[1], al, b0h[2], b0h[3]);
        mma16816(acc[2], al, b1h[0], b1h[1]);
        mma16816(acc[3], al, b1h[2], b1h[3]);
    }
}

__global__ __launch_bounds__(128) void gemmM(
    const __nv_bfloat16* __restrict__ XHg, const __nv_bfloat16* __restrict__ XLg,
    const float* __restrict__ W, float* __restrict__ Cp, int K, int kchunk)
{
    __shared__ __align__(16) __nv_bfloat16 sWH[64 * WSTR];
    __shared__ __align__(16) __nv_bfloat16 sWL[64 * WSTR];
    __shared__ __align__(16) __nv_bfloat16 sXH[32 * WSTR];
    __shared__ __align__(16) __nv_bfloat16 sXL[32 * WSTR];

    const int N  = gridDim.x * 64;
    const int n0 = blockIdx.x * 64;
    const int k0 = blockIdx.y * kchunk;
    const int tid = threadIdx.x, wid = tid >> 5, lane = tid & 31;

    const int wrow = tid >> 1;          // W row 0..63
    const int hf   = tid & 1;           // k-half (16 floats)
    const int xrow = tid >> 2;          // X row 0..31
    const int xc   = (tid & 3) * 8;     // 8 bf16 (16B) per chunk
    const float* wp = W + (size_t)(n0 + wrow) * K + k0 + hf * 16;
    const __nv_bfloat16* xhp = XHg + (size_t)xrow * K + k0 + xc;
    const __nv_bfloat16* xlp = XLg + (size_t)xrow * K + k0 + xc;

    float acc[4][4];
#pragma unroll
    for (int i = 0; i < 4; i++)
#pragma unroll
        for (int j = 0; j < 4; j++) acc[i][j] = 0.f;

    float4 wregA[4], wregB[4];
    uint4 xhA, xlA, xhB, xlB;

    const int tiles = kchunk >> 5;   // always even (>= 4)

    // prologue: tiles 0 and 1 -> register sets A and B
#pragma unroll
    for (int i = 0; i < 4; i++) wregA[i] = *(const float4*)(wp + i * 4);
    xhA = *(const uint4*)(xhp);
    xlA = *(const uint4*)(xlp);
#pragma unroll
    for (int i = 0; i < 4; i++) wregB[i] = *(const float4*)(wp + 32 + i * 4);
    xhB = *(const uint4*)(xhp + 32);
    xlB = *(const uint4*)(xlp + 32);

    for (int t = 0; t < tiles; t += 2) {
        // ---- tile t (set A) ----
        gm_stage(wregA, xhA, xlA, sWH, sWL, sXH, sXL, wrow, hf, xrow, xc);
        __syncthreads();
        if (t + 2 < tiles) {
            int kt = (t + 2) * 32;
#pragma unroll
            for (int i = 0; i < 4; i++)
                wregA[i] = *(const float4*)(wp + kt + i * 4);
            xhA = *(const uint4*)(xhp + kt);
            xlA = *(const uint4*)(xlp + kt);
        }
        gm_compute(acc, sWH, sWL, sXH, sXL, wid, lane);
        __syncthreads();

        // ---- tile t+1 (set B) ----
        gm_stage(wregB, xhB, xlB, sWH, sWL, sXH, sXL, wrow, hf, xrow, xc);
        __syncthreads();
        if (t + 3 < tiles) {
            int kt = (t + 3) * 32;
#pragma unroll
            for (int i = 0; i < 4; i++)
                wregB[i] = *(const float4*)(wp + kt + i * 4);
            xhB = *(const uint4*)(xhp + kt);
            xlB = *(const uint4*)(xlp + kt);
        }
        gm_compute(acc, sWH, sWL, sXH, sXL, wid, lane);
        __syncthreads();
    }

    // ---- epilogue: D frags -> Cp[token][n0 + wrow] ----
    {
        const int m0 = wid * 16;
        int r = lane >> 2, c2 = (lane & 3) * 2;
        float* cp = Cp + (size_t)blockIdx.y * 32 * N + n0;
#pragma unroll
        for (int nt = 0; nt < 4; nt++) {
            int tok = nt * 8 + c2;
            cp[(size_t)tok * N + m0 + r]           = acc[nt][0];
            cp[(size_t)(tok + 1) * N + m0 + r]     = acc[nt][1];
            cp[(size_t)tok * N + m0 + r + 8]       = acc[nt][2];
            cp[(size_t)(tok + 1) * N + m0 + r + 8] = acc[nt][3];
        }
    }
}

// ---------------- split-K combine + bias (f32 out) ---------------------------
__global__ void combine_kernel(
    const float* __restrict__ Cp, int KS, int N,
    const float* __restrict__ bias, float* __restrict__ out)
{
    int idx = blockIdx.x * 256 + threadIdx.x;
    int total = 32 * N;
    if (idx >= total) return;
    float s = 0.f;
#pragma unroll 4
    for (int k = 0; k < KS; k++) s += Cp[(size_t)k * total + idx];
    int m = idx / N;
    s += bias[idx - m * N];
    out[idx] = s;
}

// ---------------- split-K combine + bias + gelu -> bf16 hi/lo ----------------
__global__ void combine_gelu_bf16(
    const float* __restrict__ Cp, int KS, int N,
    const float* __restrict__ bias,
    __nv_bfloat16* __restrict__ oh, __nv_bfloat16* __restrict__ ol)
{
    int idx = blockIdx.x * 256 + threadIdx.x;
    int total = 32 * N;
    if (idx >= total) return;
    float s = 0.f;
#pragma unroll 4
    for (int k = 0; k < KS; k++) s += Cp[(size_t)k * total + idx];
    int m = idx / N;
    s += bias[idx - m * N];
    s = gelu_f(s);
    split2(s, oh[idx], ol[idx]);
}

// ---- warp/block LN helper: mean + inv-std over 8 vals/thread ----------------
__device__ __forceinline__ void block_ln_stats(
    float4 s0, float4 s1, float* red1, float* red2,
    int lane, int w, float& mean, float& inv)
{
    float lsum = s0.x + s0.y + s0.z + s0.w + s1.x + s1.y + s1.z + s1.w;
#pragma unroll
    for (int o = 16; o; o >>= 1) lsum += __shfl_xor_sync(0xffffffffu, lsum, o);
    if (lane == 0) red1[w] = lsum;
    __syncthreads();
    mean = (red1[0] + red1[1] + red1[2] + red1[3] +
            red1[4] + red1[5] + red1[6] + red1[7]) * (1.0f / H);
    float lsq = 0.f, d;
    d = s0.x - mean; lsq += d * d;  d = s0.y - mean; lsq += d * d;
    d = s0.z - mean; lsq += d * d;  d = s0.w - mean; lsq += d * d;
    d = s1.x - mean; lsq += d * d;  d = s1.y - mean; lsq += d * d;
    d = s1.z - mean; lsq += d * d;  d = s1.w - mean; lsq += d * d;
#pragma unroll
    for (int o = 16; o; o >>= 1) lsq += __shfl_xor_sync(0xffffffffu, lsq, o);
    if (lane == 0) red2[w] = lsq;
    __syncthreads();
    float var = (red2[0] + red2[1] + red2[2] + red2[3] +
                 red2[4] + red2[5] + red2[6] + red2[7]) * (1.0f / H);
    inv = rsqrtf(var + 1e-5f);
}

// ------- fused split-K combine + bias + residual + LayerNorm (+bf16) ---------
__global__ void ln_part_kernel(
    const float* __restrict__ Cp, int KS,
    const float* __restrict__ bias, const float* __restrict__ resid,
    const float* __restrict__ gg, const float* __restrict__ bb,
    float* __restrict__ out,
    __nv_bfloat16* __restrict__ oh, __nv_bfloat16* __restrict__ ol)
{
    __shared__ float red1[8];
    __shared__ float red2[8];
    int r = blockIdx.x, tid = threadIdx.x;
    int lane = tid & 31, w = tid >> 5;
    int j0 = tid * 4, j1 = tid * 4 + 1024;

    float4 s0 = make_float4(0.f, 0.f, 0.f, 0.f);
    float4 s1 = make_float4(0.f, 0.f, 0.f, 0.f);
#pragma unroll 4
    for (int k = 0; k < KS; k++) {
        const float* p = Cp + ((size_t)k * 32 + r) * H;
        float4 a = *(const float4*)&p[j0];
        float4 b = *(const float4*)&p[j1];
        s0.x += a.x; s0.y += a.y; s0.z += a.z; s0.w += a.w;
        s1.x += b.x; s1.y += b.y; s1.z += b.z; s1.w += b.w;
    }
    {
        float4 a = *(const float4*)&bias[j0];
        float4 b = *(const float4*)&bias[j1];
        s0.x += a.x; s0.y += a.y; s0.z += a.z; s0.w += a.w;
        s1.x += b.x; s1.y += b.y; s1.z += b.z; s1.w += b.w;
        a = *(const float4*)&resid[(size_t)r * H + j0];
        b = *(const float4*)&resid[(size_t)r * H + j1];
        s0.x += a.x; s0.y += a.y; s0.z += a.z; s0.w += a.w;
        s1.x += b.x; s1.y += b.y; s1.z += b.z; s1.w += b.w;
    }

    float mean, inv;
    block_ln_stats(s0, s1, red1, red2, lane, w, mean, inv);

#pragma unroll
    for (int g2 = 0; g2 < 2; g2++) {
        int j = g2 ? j1 : j0;
        float4 v = g2 ? s1 : s0;
        float4 gv = *(const float4*)&gg[j];
        float4 bv = *(const float4*)&bb[j];
        float4 o;
        o.x = (v.x - mean) * inv * gv.x + bv.x;
        o.y = (v.y - mean) * inv * gv.y + bv.y;
        o.z = (v.z - mean) * inv * gv.z + bv.z;
        o.w = (v.w - mean) * inv * gv.w + bv.w;
        *(float4*)&out[(size_t)r * H + j] = o;
        if (oh) {
            size_t ix = (size_t)r * H + j;
            split2(o.x, oh[ix + 0], ol[ix + 0]);
            split2(o.y, oh[ix + 1], ol[ix + 1]);
            split2(o.z, oh[ix + 2], ol[ix + 2]);
            split2(o.w, oh[ix + 3], ol[ix + 3]);
        }
    }
}

// -- fused: combine+bias+resid -> LN1 -> +v2 -> LN2 -> out (+bf16 split) ------
__global__ void ln_dual_kernel(
    const float* __restrict__ Cp, int KS,
    const float* __restrict__ bias, const float* __restrict__ resid,
    const float* __restrict__ g1, const float* __restrict__ b1,
    const float* __restrict__ v2,
    const float* __restrict__ g2, const float* __restrict__ b2,
    float* __restrict__ out,
    __nv_bfloat16* __restrict__ oh, __nv_bfloat16* __restrict__ ol)
{
    __shared__ float red1[8];
    __shared__ float red2[8];
    int r = blockIdx.x, tid = threadIdx.x;
    int lane = tid & 31, w = tid >> 5;
    int j0 = tid * 4, j1 = tid * 4 + 1024;

    float4 s0 = make_float4(0.f, 0.f, 0.f, 0.f);
    float4 s1 = make_float4(0.f, 0.f, 0.f, 0.f);
#pragma unroll 4
    for (int k = 0; k < KS; k++) {
        const float* p = Cp + ((size_t)k * 32 + r) * H;
        float4 a = *(const float4*)&p[j0];
        float4 b = *(const float4*)&p[j1];
        s0.x += a.x; s0.y += a.y; s0.z += a.z; s0.w += a.w;
        s1.x += b.x; s1.y += b.y; s1.z += b.z; s1.w += b.w;
    }
    {
        float4 a = *(const float4*)&bias[j0];
        float4 b = *(const float4*)&bias[j1];
        s0.x += a.x; s0.y += a.y; s0.z += a.z; s0.w += a.w;
        s1.x += b.x; s1.y += b.y; s1.z += b.z; s1.w += b.w;
        a = *(const float4*)&resid[(size_t)r * H + j0];
        b = *(const float4*)&resid[(size_t)r * H + j1];
        s0.x += a.x; s0.y += a.y; s0.z += a.z; s0.w += a.w;
        s1.x += b.x; s1.y += b.y; s1.z += b.z; s1.w += b.w;
    }

    float mean, inv;
    block_ln_stats(s0, s1, red1, red2, lane, w, mean, inv);

    float4 t0, t1;
    {
        float4 gv = *(const float4*)&g1[j0];
        float4 bv = *(const float4*)&b1[j0];
        float4 vv = *(const float4*)&v2[j0];
        t0.x = (s0.x - mean) * inv * gv.x + bv.x + vv.x;
        t0.y = (s0.y - mean) * inv * gv.y + bv.y + vv.y;
        t0.z = (s0.z - mean) * inv * gv.z + bv.z + vv.z;
        t0.w = (s0.w - mean) * inv * gv.w + bv.w + vv.w;
        gv = *(const float4*)&g1[j1];
        bv = *(const float4*)&b1[j1];
        vv = *(const float4*)&v2[j1];
        t1.x = (s1.x - mean) * inv * gv.x + bv.x + vv.x;
        t1.y = (s1.y - mean) * inv * gv.y + bv.y + vv.y;
        t1.z = (s1.z - mean) * inv * gv.z + bv.z + vv.z;
        t1.w = (s1.w - mean) * inv * gv.w + bv.w + vv.w;
    }
    __syncthreads();

    float mean2, inv2;
    block_ln_stats(t0, t1, red1, red2, lane, w, mean2, inv2);

#pragma unroll
    for (int gq = 0; gq < 2; gq++) {
        int j = gq ? j1 : j0;
        float4 v = gq ? t1 : t0;
        float4 gv = *(const float4*)&g2[j];
        float4 bv = *(const float4*)&b2[j];
        float4 o;
        o.x = (v.x - mean2) * inv2 * gv.x + bv.x;
        o.y = (v.y - mean2) * inv2 * gv.y + bv.y;
        o.z = (v.z - mean2) * inv2 * gv.z + bv.z;
        o.w = (v.w - mean2) * inv2 * gv.w + bv.w;
        *(float4*)&out[(size_t)r * H + j] = o;
        size_t ix = (size_t)r * H + j;
        split2(o.x, oh[ix + 0], ol[ix + 0]);
        split2(o.y, oh[ix + 1], ol[ix + 1]);
        split2(o.z, oh[ix + 2], ol[ix + 2]);
        split2(o.w, oh[ix + 3], ol[ix + 3]);
    }
}

// ---------------- batched cross-attn GEMV ------------------------------------
__global__ void gemv_ca(const float* __restrict__ xin, const float* __restrict__ Wt,
                        const float* __restrict__ bias, float* __restrict__ out, int mode)
{
    int n = blockIdx.x * 8 + (threadIdx.x >> 5);
    int lane = threadIdx.x & 31;
    int l = n >> 11, r = n & 2047;
    const float* w;
    const float* x;
    float b;
    if (mode == 0) {
        w = Wt + ((size_t)l * 3 * H + 2 * H + r) * H;
        x = xin;
        b = bias[(size_t)l * 3 * H + 2 * H + r];
    } else {
        w = Wt + ((size_t)l * H + r) * H;
        x = xin + (size_t)l * H;
        b = bias[(size_t)l * H + r];
    }
    float s = 0.f;
#pragma unroll 8
    for (int k = lane * 4; k < H; k += 128) {
        float4 a = *(const float4*)&x[k];
        float4 bw = *(const float4*)&w[k];
        s += a.x * bw.x + a.y * bw.y + a.z * bw.z + a.w * bw.w;
    }
#pragma unroll
    for (int o = 16; o; o >>= 1) s += __shfl_xor_sync(0xffffffffu, s, o);
    if (lane == 0) out[n] = s + b;
}

// ---------------- plain GEMV (size predictor layer 1) ------------------------
__global__ void gemv_kernel(
    const float* __restrict__ x, const float* __restrict__ W,
    const float* __restrict__ bias, float* __restrict__ out, int K, int act)
{
    int n = blockIdx.x * 8 + (threadIdx.x >> 5);
    int lane = threadIdx.x & 31;
    const float* w = W + (size_t)n * K;
    float s = 0.f;
#pragma unroll 8
    for (int k = lane * 4; k < K; k += 128) {
        float4 a = *(const float4*)&x[k];
        float4 b = *(const float4*)&w[k];
        s += a.x * b.x + a.y * b.y + a.z * b.z + a.w * b.w;
    }
#pragma unroll
    for (int o = 16; o; o >>= 1) s += __shfl_xor_sync(0xffffffffu, s, o);
    if (lane == 0) {
        s += bias[n];
        if (act) s = gelu_f(s);
        out[n] = s;
    }
}

// ---------------- self-attention (outputs bf16 split) ------------------------
__global__ void attn_kernel(const float* __restrict__ qkv,
                            __nv_bfloat16* __restrict__ oh,
                            __nv_bfloat16* __restrict__ ol)
{
    int h = blockIdx.x, bq = blockIdx.y;
    int tid = threadIdx.x;
    __shared__ float sc[8][32];

    int il = tid >> 5;
    int i = bq * 8 + il;
    int j = tid & 31;
    const float* q = qkv + (size_t)i * (3 * H) + h * DHD;
    const float* k = qkv + (size_t)j * (3 * H) + H + h * DHD;
    float s = 0.f;
#pragma unroll 8
    for (int d = 0; d < DHD; d += 4) {
        float4 a = *(const float4*)&q[d];
        float4 b = *(const float4*)&k[d];
        s += a.x * b.x + a.y * b.y + a.z * b.z + a.w * b.w;
    }
    s *= 0.0625f;
    float mx = s;
#pragma unroll
    for (int off = 16; off; off >>= 1) mx = fmaxf(mx, __shfl_xor_sync(0xffffffffu, mx, off));
    float p = expf(s - mx);
    float sum = p;
#pragma unroll
    for (int off = 16; off; off >>= 1) sum += __shfl_xor_sync(0xffffffffu, sum, off);
    sc[il][j] = p / sum;
    __syncthreads();

#pragma unroll
    for (int r = 0; r < 8; r++) {
        int u = tid + 256 * r;
        int ir = u >> 8;
        int d = u & 255;
        const float* vb = qkv + 2 * H + h * DHD + d;
        float acc = 0.f;
#pragma unroll
        for (int jj = 0; jj < 32; jj++)
            acc = fmaf(sc[ir][jj], vb[(size_t)jj * (3 * H)], acc);
        size_t ix = (size_t)(bq * 8 + ir) * H + h * DHD + d;
        split2(acc, oh[ix], ol[ix]);
    }
}

// ---------------- decoder input embedding (+ bf16 split) ---------------------
__global__ void embed_kernel(const int* __restrict__ tb,
                             const float* __restrict__ bemb,
                             const float* __restrict__ pemb,
                             float* __restrict__ x,
                             __nv_bfloat16* __restrict__ oh,
                             __nv_bfloat16* __restrict__ ol)
{
    int idx = blockIdx.x * 256 + threadIdx.x;
    int m = idx >> 11, j = idx & 2047;
    int tok = (m == 0) ? 256 : tb[m - 1];
    float v = bemb[(size_t)tok * H + j] + pemb[idx];
    x[idx] = v;
    split2(v, oh[idx], ol[idx]);
}

// ---------------- size predictor head 2 + softmax ----------------------------
__global__ void sp2_softmax(const float* __restrict__ hv, const float* __restrict__ W,
                            const float* __restrict__ bias, float* __restrict__ out)
{
    __shared__ float lg[33];
    int tid = threadIdx.x, w = tid >> 5, lane = tid & 31;
    for (int n = w; n < 33; n += 8) {
        const float* wr = W + (size_t)n * 1024;
        float s = 0.f;
#pragma unroll 8
        for (int k = lane * 4; k < 1024; k += 128) {
            float4 a = *(const float4*)&hv[k];
            float4 b = *(const float4*)&wr[k];
            s += a.x * b.x + a.y * b.y + a.z * b.z + a.w * b.w;
        }
#pragma unroll
        for (int o = 16; o; o >>= 1) s += __shfl_xor_sync(0xffffffffu, s, o);
        if (lane == 0) lg[n] = s + bias[n];
    }
    __syncthreads();
    if (tid == 0) {
        float mx = -1e30f;
        for (int n = 0; n < 33; n++) mx = fmaxf(mx, lg[n]);
        float sum = 0.f;
        for (int n = 0; n < 33; n++) { float e = expf(lg[n] - mx); lg[n] = e; sum += e; }
        float inv = 1.0f / sum;
        for (int n = 0; n < 33; n++) out[n] = lg[n] * inv;
    }
}

// =============================================================================
extern "C" void kernel_launch(void* const* d_in, const int* in_sizes, int n_in,
                              void* d_out, int out_size)
{
    const float* pe     = (const float*)d_in[0];
    const int*   tb     = (const int*)  d_in[1];
    const float* sp_w1  = (const float*)d_in[2];
    const float* sp_b1  = (const float*)d_in[3];
    const float* sp_w2  = (const float*)d_in[4];
    const float* sp_b2  = (const float*)d_in[5];
    const float* bemb   = (const float*)d_in[6];
    const float* pemb   = (const float*)d_in[7];
    const float* proj_w = (const float*)d_in[8];
    const float* proj_b = (const float*)d_in[9];
    const float* sa_in_w  = (const float*)d_in[10];
    const float* sa_in_b  = (const float*)d_in[11];
    const float* sa_out_w = (const float*)d_in[12];
    const float* sa_out_b = (const float*)d_in[13];
    const float* ca_in_w  = (const float*)d_in[14];
    const float* ca_in_b  = (const float*)d_in[15];
    const float* ca_out_w = (const float*)d_in[16];
    const float* ca_out_b = (const float*)d_in[17];
    const float* ff_w1 = (const float*)d_in[18];
    const float* ff_b1 = (const float*)d_in[19];
    const float* ff_w2 = (const float*)d_in[20];
    const float* ff_b2 = (const float*)d_in[21];
    const float* ln1_g = (const float*)d_in[22];
    const float* ln1_b = (const float*)d_in[23];
    const float* ln2_g = (const float*)d_in[24];
    const float* ln2_b = (const float*)d_in[25];
    const float* ln3_g = (const float*)d_in[26];
    const float* ln3_b = (const float*)d_in[27];

    float *x, *qkv, *part, *v1, *v2, *hbuf;
    __nv_bfloat16 *xh, *xl, *ah, *al, *gh, *gl;
    cudaGetSymbolAddress((void**)&x, g_x);
    cudaGetSymbolAddress((void**)&qkv, g_qkv);
    cudaGetSymbolAddress((void**)&part, g_part);
    cudaGetSymbolAddress((void**)&v1, g_v1);
    cudaGetSymbolAddress((void**)&v2, g_v2);
    cudaGetSymbolAddress((void**)&hbuf, g_h);
    cudaGetSymbolAddress((void**)&xh, g_xh);
    cudaGetSymbolAddress((void**)&xl, g_xl);
    cudaGetSymbolAddress((void**)&ah, g_ah);
    cudaGetSymbolAddress((void**)&al, g_al);
    cudaGetSymbolAddress((void**)&gh, g_gh);
    cudaGetSymbolAddress((void**)&gl, g_gl);

    // one-time side-stream/event infra (host objects, no device memory)
    static cudaStream_t s1 = nullptr;
    static cudaEvent_t evFork = nullptr, evJoin = nullptr, evEnd = nullptr;
    static cudaEvent_t evG[9];
    if (!s1) {
        cudaStreamCreateWithFlags(&s1, cudaStreamNonBlocking);
        cudaEventCreateWithFlags(&evFork, cudaEventDisableTiming);
        cudaEventCreateWithFlags(&evJoin, cudaEventDisableTiming);
        cudaEventCreateWithFlags(&evEnd, cudaEventDisableTiming);
        for (int i = 0; i < 9; i++)
            cudaEventCreateWithFlags(&evG[i], cudaEventDisableTiming);
    }

    float* out = (float*)d_out;
    const int PG = 256, PT = 256;

    // ---- fork: head + ca vectors + first prefetches on side stream ----------
    cudaEventRecord(evFork, 0);
    cudaStreamWaitEvent(s1, evFork, 0);
    gemv_kernel<<<1024 / 8, 256, 0, s1>>>(pe, sp_w1, sp_b1, hbuf, 2048, 1);
    sp2_softmax<<<1, 256, 0, s1>>>(hbuf, sp_w2, sp_b2, out);
    gemv_ca<<<(NLAYER * H) / 8, 256, 0, s1>>>(pe, ca_in_w, ca_in_b, v1, 0);
    gemv_ca<<<(NLAYER * H) / 8, 256, 0, s1>>>(v1, ca_out_w, ca_out_b, v2, 1);
    cudaEventRecord(evJoin, s1);
    // warm layer-0 sa_out + ff_w1 while sa_in0 computes
    prefetch_l2<<<PG, PT, 0, s1>>>(sa_out_w, H * H);
    prefetch_l2<<<PG, PT, 0, s1>>>(ff_w1, 4 * H * H);

    // ---- main decoder chain (default stream), prefetches interleaved --------
    embed_kernel<<<(S * H) / 256, 256>>>(tb, bemb, pemb, x, xh, xl);

    for (int l = 0; l < 3; l++) {
        // --- self attention ---
        gemmM<<<dim3(96, 8), 128>>>(xh, xl, sa_in_w + (size_t)l * 3 * H * H,
                                    part, H, 256);
        cudaEventRecord(evG[l * 3 + 0], 0);
        // after sa_in[l]: warm ff_w2[l]   (record happened above -> legal wait)
        cudaStreamWaitEvent(s1, evG[l * 3 + 0], 0);
        prefetch_l2<<<PG, PT, 0, s1>>>(ff_w2 + (size_t)l * 4 * H * H, 4 * H * H);

        combine_kernel<<<(32 * 6144) / 256, 256>>>(part, 8, 6144,
                                                   sa_in_b + (size_t)l * 3 * H, qkv);
        attn_kernel<<<dim3(8, 4), 256>>>(qkv, ah, al);
        gemmM<<<dim3(32, 16), 128>>>(ah, al, sa_out_w + (size_t)l * H * H,
                                     part, H, 128);

        if (l == 0) cudaStreamWaitEvent(0, evJoin, 0);  // v2 ready before LN2 use

        // --- fused LN1 + cross-attn(+v2) + LN2 ---
        ln_dual_kernel<<<32, 256>>>(part, 16, sa_out_b + (size_t)l * H, x,
                                    ln1_g + (size_t)l * H, ln1_b + (size_t)l * H,
                                    v2 + (size_t)l * H,
                                    ln2_g + (size_t)l * H, ln2_b + (size_t)l * H,
                                    x, xh, xl);

        // --- feed forward ---
        gemmM<<<dim3(128, 8), 128>>>(xh, xl, ff_w1 + (size_t)l * 4 * H * H,
                                     part, H, 256);
        cudaEventRecord(evG[l * 3 + 1], 0);
        // after ff1[l]: warm next layer's sa_in + sa_out (or proj for last layer)
        cudaStreamWaitEvent(s1, evG[l * 3 + 1], 0);
        if (l < 2) {
            prefetch_l2<<<PG, PT, 0, s1>>>(sa_in_w + (size_t)(l + 1) * 3 * H * H,
                                           3 * H * H);
            prefetch_l2<<<PG, PT, 0, s1>>>(sa_out_w + (size_t)(l + 1) * H * H, H * H);
        } else {
            prefetch_l2<<<PG, PT, 0, s1>>>(proj_w, 256 * H);
        }

        combine_gelu_bf16<<<(32 * 8192) / 256, 256>>>(part, 8, 8192,
                                                      ff_b1 + (size_t)l * 4 * H, gh, gl);
        gemmM<<<dim3(32, 16), 128>>>(gh, gl, ff_w2 + (size_t)l * H * 4 * H,
                                     part, 4 * H, 512);
        cudaEventRecord(evG[l * 3 + 2], 0);
        // after ff2[l]: warm next layer's ff_w1
        if (l < 2) {
            cudaStreamWaitEvent(s1, evG[l * 3 + 2], 0);
            prefetch_l2<<<PG, PT, 0, s1>>>(ff_w1 + (size_t)(l + 1) * 4 * H * H,
                                           4 * H * H);
        }

        ln_part_kernel<<<32, 256>>>(part, 16, ff_b2 + (size_t)l * H, x,
                                    ln3_g + (size_t)l * H, ln3_b + (size_t)l * H,
                                    x, xh, xl);
    }

    // join side stream so the captured graph is fully connected
    cudaEventRecord(evEnd, s1);
    cudaStreamWaitEvent(0, evEnd, 0);

    // byte logits
    gemmM<<<dim3(4, 16), 128>>>(xh, xl, proj_w, part, H, 128);
    combine_kernel<<<(32 * 256) / 256, 256>>>(part, 16, 256, proj_b, out + 33);
}

// round 16
// speedup vs baseline: 1.4554x; 1.4554x over previous
#include <cuda_runtime.h>
#include <cuda_bf16.h>
#include <math.h>
#include <stdint.h>

#define H 2048
#define S 32
#define NHEAD 8
#define DHD 256
#define NLAYER 3

// ---------------- scratch (device globals; no allocation allowed) ------------
__device__ float g_x[S * H];
__device__ float g_qkv[S * 3 * H];
__device__ float g_part[4194304];
__device__ float g_v1[NLAYER * H];
__device__ float g_v2[NLAYER * H];
__device__ float g_h[1024];
__device__ __nv_bfloat16 g_xh[S * H];
__device__ __nv_bfloat16 g_xl[S * H];
__device__ __nv_bfloat16 g_ah[S * H];
__device__ __nv_bfloat16 g_al[S * H];
__device__ __nv_bfloat16 g_gh[S * 4 * H];
__device__ __nv_bfloat16 g_gl[S * 4 * H];

__device__ __forceinline__ float gelu_f(float v) {
    return 0.5f * v * (1.0f + erff(v * 0.70710678118654752f));
}
__device__ __forceinline__ void split2(float x, __nv_bfloat16& h, __nv_bfloat16& l) {
    unsigned u = __float_as_uint(x);
    h = __ushort_as_bfloat16((unsigned short)(u >> 16));
    l = __float2bfloat16(x - __uint_as_float(u & 0xFFFF0000u));
}

// ======================= warp-specialized HMMA GEMM ==========================
// Cp[32,N] slice = X[32,Kslice] @ W[N,Kslice]^T as D[64 wrow, 32 tok] per block.
// 256 threads: warps 0-3 consume (ldsm+MMA), warps 4-7 produce (LDG+cvt+STS).
// fp32 emulated by bf16 hi/lo split: hh+hl+lh passes. Double-buffered smem.

#define WSTR 40   // padded row stride (bf16): 80B; 16B-aligned rows, 0-conflict
#define WTILE (64 * WSTR)
#define XTILE (32 * WSTR)

__device__ __forceinline__ uint32_t sptr(const void* p) {
    return (uint32_t)__cvta_generic_to_shared(p);
}
__device__ __forceinline__ void barsync() {
    asm volatile("bar.sync 0;" ::: "memory");
}
__device__ __forceinline__ void ldsm4(uint32_t* r, uint32_t a) {
    asm volatile("ldmatrix.sync.aligned.m8n8.x4.shared.b16 {%0,%1,%2,%3}, [%4];"
                 : "=r"(r[0]), "=r"(r[1]), "=r"(r[2]), "=r"(r[3]) : "r"(a));
}
__device__ __forceinline__ void mma16816(float* d, const uint32_t* a,
                                         uint32_t b0, uint32_t b1) {
    asm volatile(
        "mma.sync.aligned.m16n8k16.row.col.f32.bf16.bf16.f32 "
        "{%0,%1,%2,%3}, {%4,%5,%6,%7}, {%8,%9}, {%0,%1,%2,%3};"
        : "+f"(d[0]), "+f"(d[1]), "+f"(d[2]), "+f"(d[3])
        : "r"(a[0]), "r"(a[1]), "r"(a[2]), "r"(a[3]), "r"(b0), "r"(b1));
}

// stage one 32-k tile from registers into smem buffer (W f32 -> bf16 hi/lo)
__device__ __forceinline__ void gm_stage(
    const float4* wreg, uint4 xh4, uint4 xl4,
    __nv_bfloat16* sWH, __nv_bfloat16* sWL,
    __nv_bfloat16* sXH, __nv_bfloat16* sXL,
    int wrow, int hf, int xrow, int xc)
{
#pragma unroll
    for (int i = 0; i < 4; i++) {
        float4 f = wreg[i];
        unsigned u0 = __float_as_uint(f.x), u1 = __float_as_uint(f.y);
        unsigned u2 = __float_as_uint(f.z), u3 = __float_as_uint(f.w);
        unsigned h01 = __byte_perm(u0, u1, 0x7632);
        unsigned h23 = __byte_perm(u2, u3, 0x7632);
        float l0 = f.x - __uint_as_float(u0 & 0xFFFF0000u);
        float l1 = f.y - __uint_as_float(u1 & 0xFFFF0000u);
        float l2 = f.z - __uint_as_float(u2 & 0xFFFF0000u);
        float l3 = f.w - __uint_as_float(u3 & 0xFFFF0000u);
        unsigned l01, l23;
        asm("cvt.rn.bf16x2.f32 %0, %1, %2;" : "=r"(l01) : "f"(l1), "f"(l0));
        asm("cvt.rn.bf16x2.f32 %0, %1, %2;" : "=r"(l23) : "f"(l3), "f"(l2));
        int e = wrow * WSTR + hf * 16 + i * 4;
        *(uint2*)&sWH[e] = make_uint2(h01, h23);
        *(uint2*)&sWL[e] = make_uint2(l01, l23);
    }
    int e = xrow * WSTR + xc;
    *(uint4*)&sXH[e] = xh4;
    *(uint4*)&sXL[e] = xl4;
}

// consume a staged tile: per warp 16 W-rows, 2 k-steps x (6 ldsm + 12 mma)
__device__ __forceinline__ void gm_compute(
    float acc[4][4],
    const __nv_bfloat16* sWH, const __nv_bfloat16* sWL,
    const __nv_bfloat16* sXH, const __nv_bfloat16* sXL,
    int wid, int lane)
{
    const int m0 = wid * 16;
#pragma unroll
    for (int s = 0; s < 2; s++) {
        uint32_t ah[4], al[4], b0h[4], b1h[4], b0l[4], b1l[4];
        {
            int arow = m0 + (lane & 15);
            int acol = s * 16 + ((lane >> 4) << 3);
            ldsm4(ah, sptr(&sWH[arow * WSTR + acol]));
            ldsm4(al, sptr(&sWL[arow * WSTR + acol]));
        }
        {
            int brow = ((lane >> 4) << 3) + (lane & 7);
            int bcol = s * 16 + (lane & 8);
            ldsm4(b0h, sptr(&sXH[brow * WSTR + bcol]));
            ldsm4(b1h, sptr(&sXH[(16 + brow) * WSTR + bcol]));
            ldsm4(b0l, sptr(&sXL[brow * WSTR + bcol]));
            ldsm4(b1l, sptr(&sXL[(16 + brow) * WSTR + bcol]));
        }
        // hh
        mma16816(acc[0], ah, b0h[0], b0h[1]);
        mma16816(acc[1], ah, b0h[2], b0h[3]);
        mma16816(acc[2], ah, b1h[0], b1h[1]);
        mma16816(acc[3], ah, b1h[2], b1h[3]);
        // hl
        mma16816(acc[0], ah, b0l[0], b0l[1]);
        mma16816(acc[1], ah, b0l[2], b0l[3]);
        mma16816(acc[2], ah, b1l[0], b1l[1]);
        mma16816(acc[3], ah, b1l[2], b1l[3]);
        // lh
        mma16816(acc[0], al, b0h[0], b0h[1]);
        mma16816(acc[1], al, b0h[2], b0h[3]);
        mma16816(acc[2], al, b1h[0], b1h[1]);
        mma16816(acc[3], al, b1h[2], b1h[3]);
    }
}

// NOTE: all launches use even tiles counts (kchunk/32 in {4, 8, 16}).
__global__ __launch_bounds__(256) void gemmW(
    const __nv_bfloat16* __restrict__ XHg, const __nv_bfloat16* __restrict__ XLg,
    const float* __restrict__ W, float* __restrict__ Cp, int K, int kchunk)
{
    __shared__ __align__(16) __nv_bfloat16 sWH[2][WTILE];
    __shared__ __align__(16) __nv_bfloat16 sWL[2][WTILE];
    __shared__ __align__(16) __nv_bfloat16 sXH[2][XTILE];
    __shared__ __align__(16) __nv_bfloat16 sXL[2][XTILE];

    const int N  = gridDim.x * 64;
    const int n0 = blockIdx.x * 64;
    const int k0 = blockIdx.y * kchunk;
    const int tid = threadIdx.x, wid = tid >> 5, lane = tid & 31;
    const int tiles = kchunk >> 5;    // even, >= 4

    if (wid >= 4) {
        // =================== producer warps (4..7) ===========================
        const int pt   = tid - 128;         // 0..127
        const int wrow = pt >> 1;           // W row 0..63
        const int hf   = pt & 1;            // k-half (16 floats)
        const int xrow = pt >> 2;           // X row 0..31
        const int xc   = (pt & 3) * 8;      // 8 bf16 (16B) per chunk
        const float* wp = W + (size_t)(n0 + wrow) * K + k0 + hf * 16;
        const __nv_bfloat16* xhp = XHg + (size_t)xrow * K + k0 + xc;
        const __nv_bfloat16* xlp = XLg + (size_t)xrow * K + k0 + xc;

        float4 wregA[4], wregB[4];
        uint4 xhA, xlA, xhB, xlB;

        // prologue: load tile0 (A) and tile1 (B); stage tile0 -> buf0
#pragma unroll
        for (int i = 0; i < 4; i++) wregA[i] = *(const float4*)(wp + i * 4);
        xhA = *(const uint4*)(xhp);
        xlA = *(const uint4*)(xlp);
#pragma unroll
        for (int i = 0; i < 4; i++) wregB[i] = *(const float4*)(wp + 32 + i * 4);
        xhB = *(const uint4*)(xhp + 32);
        xlB = *(const uint4*)(xlp + 32);
        gm_stage(wregA, xhA, xlA, sWH[0], sWL[0], sXH[0], sXL[0], wrow, hf, xrow, xc);

        for (int t = 0; t < tiles; t += 2) {
            barsync();   // consumers done with buf1(t-1); buf0(t) visible
            // stage tile t+1 -> buf1 while consumers compute buf0
            gm_stage(wregB, xhB, xlB, sWH[1], sWL[1], sXH[1], sXL[1],
                     wrow, hf, xrow, xc);
            if (t + 2 < tiles) {            // prefetch tile t+2 -> set A
                int kt = (t + 2) * 32;
#pragma unroll
                for (int i = 0; i < 4; i++)
                    wregA[i] = *(const float4*)(wp + kt + i * 4);
                xhA = *(const uint4*)(xhp + kt);
                xlA = *(const uint4*)(xlp + kt);
            }
            barsync();   // consumers done with buf0(t); buf1(t+1) visible
            if (t + 2 < tiles) {
                // stage tile t+2 -> buf0 while consumers compute buf1
                gm_stage(wregA, xhA, xlA, sWH[0], sWL[0], sXH[0], sXL[0],
                         wrow, hf, xrow, xc);
                if (t + 3 < tiles) {        // prefetch tile t+3 -> set B
                    int kt = (t + 3) * 32;
#pragma unroll
                    for (int i = 0; i < 4; i++)
                        wregB[i] = *(const float4*)(wp + kt + i * 4);
                    xhB = *(const uint4*)(xhp + kt);
                    xlB = *(const uint4*)(xlp + kt);
                }
            }
        }
    } else {
        // =================== consumer warps (0..3) ===========================
        float acc[4][4];
#pragma unroll
        for (int i = 0; i < 4; i++)
#pragma unroll
            for (int j = 0; j < 4; j++) acc[i][j] = 0.f;

        for (int t = 0; t < tiles; t += 2) {
            barsync();   // buf0 = tile t ready
            gm_compute(acc, sWH[0], sWL[0], sXH[0], sXL[0], wid, lane);
            barsync();   // buf1 = tile t+1 ready
            gm_compute(acc, sWH[1], sWL[1], sXH[1], sXL[1], wid, lane);
        }

        // epilogue: D frags -> Cp[token][n0 + wrow]
        const int m0 = wid * 16;
        int r = lane >> 2, c2 = (lane & 3) * 2;
        float* cp = Cp + (size_t)blockIdx.y * 32 * N + n0;
#pragma unroll
        for (int nt = 0; nt < 4; nt++) {
            int tok = nt * 8 + c2;
            cp[(size_t)tok * N + m0 + r]           = acc[nt][0];
            cp[(size_t)(tok + 1) * N + m0 + r]     = acc[nt][1];
            cp[(size_t)tok * N + m0 + r + 8]       = acc[nt][2];
            cp[(size_t)(tok + 1) * N + m0 + r + 8] = acc[nt][3];
        }
    }
}

// ---------------- split-K combine + bias (f32 out) ---------------------------
__global__ void combine_kernel(
    const float* __restrict__ Cp, int KS, int N,
    const float* __restrict__ bias, float* __restrict__ out)
{
    int idx = blockIdx.x * 256 + threadIdx.x;
    int total = 32 * N;
    if (idx >= total) return;
    float s = 0.f;
#pragma unroll 4
    for (int k = 0; k < KS; k++) s += Cp[(size_t)k * total + idx];
    int m = idx / N;
    s += bias[idx - m * N];
    out[idx] = s;
}

// ---------------- split-K combine + bias + gelu -> bf16 hi/lo ----------------
__global__ void combine_gelu_bf16(
    const float* __restrict__ Cp, int KS, int N,
    const float* __restrict__ bias,
    __nv_bfloat16* __restrict__ oh, __nv_bfloat16* __restrict__ ol)
{
    int idx = blockIdx.x * 256 + threadIdx.x;
    int total = 32 * N;
    if (idx >= total) return;
    float s = 0.f;
#pragma unroll 4
    for (int k = 0; k < KS; k++) s += Cp[(size_t)k * total + idx];
    int m = idx / N;
    s += bias[idx - m * N];
    s = gelu_f(s);
    split2(s, oh[idx], ol[idx]);
}

// ---- warp/block LN helper: mean + inv-std over 8 vals/thread ----------------
__device__ __forceinline__ void block_ln_stats(
    float4 s0, float4 s1, float* red1, float* red2,
    int lane, int w, float& mean, float& inv)
{
    float lsum = s0.x + s0.y + s0.z + s0.w + s1.x + s1.y + s1.z + s1.w;
#pragma unroll
    for (int o = 16; o; o >>= 1) lsum += __shfl_xor_sync(0xffffffffu, lsum, o);
    if (lane == 0) red1[w] = lsum;
    __syncthreads();
    mean = (red1[0] + red1[1] + red1[2] + red1[3] +
            red1[4] + red1[5] + red1[6] + red1[7]) * (1.0f / H);
    float lsq = 0.f, d;
    d = s0.x - mean; lsq += d * d;  d = s0.y - mean; lsq += d * d;
    d = s0.z - mean; lsq += d * d;  d = s0.w - mean; lsq += d * d;
    d = s1.x - mean; lsq += d * d;  d = s1.y - mean; lsq += d * d;
    d = s1.z - mean; lsq += d * d;  d = s1.w - mean; lsq += d * d;
#pragma unroll
    for (int o = 16; o; o >>= 1) lsq += __shfl_xor_sync(0xffffffffu, lsq, o);
    if (lane == 0) red2[w] = lsq;
    __syncthreads();
    float var = (red2[0] + red2[1] + red2[2] + red2[3] +
                 red2[4] + red2[5] + red2[6] + red2[7]) * (1.0f / H);
    inv = rsqrtf(var + 1e-5f);
}

// ------- fused split-K combine + bias + residual + LayerNorm (+bf16) ---------
__global__ void ln_part_kernel(
    const float* __restrict__ Cp, int KS,
    const float* __restrict__ bias, const float* __restrict__ resid,
    const float* __restrict__ gg, const float* __restrict__ bb,
    float* __restrict__ out,
    __nv_bfloat16* __restrict__ oh, __nv_bfloat16* __restrict__ ol)
{
    __shared__ float red1[8];
    __shared__ float red2[8];
    int r = blockIdx.x, tid = threadIdx.x;
    int lane = tid & 31, w = tid >> 5;
    int j0 = tid * 4, j1 = tid * 4 + 1024;

    float4 s0 = make_float4(0.f, 0.f, 0.f, 0.f);
    float4 s1 = make_float4(0.f, 0.f, 0.f, 0.f);
#pragma unroll 4
    for (int k = 0; k < KS; k++) {
        const float* p = Cp + ((size_t)k * 32 + r) * H;
        float4 a = *(const float4*)&p[j0];
        float4 b = *(const float4*)&p[j1];
        s0.x += a.x; s0.y += a.y; s0.z += a.z; s0.w += a.w;
        s1.x += b.x; s1.y += b.y; s1.z += b.z; s1.w += b.w;
    }
    {
        float4 a = *(const float4*)&bias[j0];
        float4 b = *(const float4*)&bias[j1];
        s0.x += a.x; s0.y += a.y; s0.z += a.z; s0.w += a.w;
        s1.x += b.x; s1.y += b.y; s1.z += b.z; s1.w += b.w;
        a = *(const float4*)&resid[(size_t)r * H + j0];
        b = *(const float4*)&resid[(size_t)r * H + j1];
        s0.x += a.x; s0.y += a.y; s0.z += a.z; s0.w += a.w;
        s1.x += b.x; s1.y += b.y; s1.z += b.z; s1.w += b.w;
    }

    float mean, inv;
    block_ln_stats(s0, s1, red1, red2, lane, w, mean, inv);

#pragma unroll
    for (int g2 = 0; g2 < 2; g2++) {
        int j = g2 ? j1 : j0;
        float4 v = g2 ? s1 : s0;
        float4 gv = *(const float4*)&gg[j];
        float4 bv = *(const float4*)&bb[j];
        float4 o;
        o.x = (v.x - mean) * inv * gv.x + bv.x;
        o.y = (v.y - mean) * inv * gv.y + bv.y;
        o.z = (v.z - mean) * inv * gv.z + bv.z;
        o.w = (v.w - mean) * inv * gv.w + bv.w;
        *(float4*)&out[(size_t)r * H + j] = o;
        if (oh) {
            size_t ix = (size_t)r * H + j;
            split2(o.x, oh[ix + 0], ol[ix + 0]);
            split2(o.y, oh[ix + 1], ol[ix + 1]);
            split2(o.z, oh[ix + 2], ol[ix + 2]);
            split2(o.w, oh[ix + 3], ol[ix + 3]);
        }
    }
}

// -- fused: combine+bias+resid -> LN1 -> +v2 -> LN2 -> out (+bf16 split) ------
__global__ void ln_dual_kernel(
    const float* __restrict__ Cp, int KS,
    const float* __restrict__ bias, const float* __restrict__ resid,
    const float* __restrict__ g1, const float* __restrict__ b1,
    const float* __restrict__ v2,
    const float* __restrict__ g2, const float* __restrict__ b2,
    float* __restrict__ out,
    __nv_bfloat16* __restrict__ oh, __nv_bfloat16* __restrict__ ol)
{
    __shared__ float red1[8];
    __shared__ float red2[8];
    int r = blockIdx.x, tid = threadIdx.x;
    int lane = tid & 31, w = tid >> 5;
    int j0 = tid * 4, j1 = tid * 4 + 1024;

    float4 s0 = make_float4(0.f, 0.f, 0.f, 0.f);
    float4 s1 = make_float4(0.f, 0.f, 0.f, 0.f);
#pragma unroll 4
    for (int k = 0; k < KS; k++) {
        const float* p = Cp + ((size_t)k * 32 + r) * H;
        float4 a = *(const float4*)&p[j0];
        float4 b = *(const float4*)&p[j1];
        s0.x += a.x; s0.y += a.y; s0.z += a.z; s0.w += a.w;
        s1.x += b.x; s1.y += b.y; s1.z += b.z; s1.w += b.w;
    }
    {
        float4 a = *(const float4*)&bias[j0];
        float4 b = *(const float4*)&bias[j1];
        s0.x += a.x; s0.y += a.y; s0.z += a.z; s0.w += a.w;
        s1.x += b.x; s1.y += b.y; s1.z += b.z; s1.w += b.w;
        a = *(const float4*)&resid[(size_t)r * H + j0];
        b = *(const float4*)&resid[(size_t)r * H + j1];
        s0.x += a.x; s0.y += a.y; s0.z += a.z; s0.w += a.w;
        s1.x += b.x; s1.y += b.y; s1.z += b.z; s1.w += b.w;
    }

    float mean, inv;
    block_ln_stats(s0, s1, red1, red2, lane, w, mean, inv);

    float4 t0, t1;
    {
        float4 gv = *(const float4*)&g1[j0];
        float4 bv = *(const float4*)&b1[j0];
        float4 vv = *(const float4*)&v2[j0];
        t0.x = (s0.x - mean) * inv * gv.x + bv.x + vv.x;
        t0.y = (s0.y - mean) * inv * gv.y + bv.y + vv.y;
        t0.z = (s0.z - mean) * inv * gv.z + bv.z + vv.z;
        t0.w = (s0.w - mean) * inv * gv.w + bv.w + vv.w;
        gv = *(const float4*)&g1[j1];
        bv = *(const float4*)&b1[j1];
        vv = *(const float4*)&v2[j1];
        t1.x = (s1.x - mean) * inv * gv.x + bv.x + vv.x;
        t1.y = (s1.y - mean) * inv * gv.y + bv.y + vv.y;
        t1.z = (s1.z - mean) * inv * gv.z + bv.z + vv.z;
        t1.w = (s1.w - mean) * inv * gv.w + bv.w + vv.w;
    }
    __syncthreads();

    float mean2, inv2;
    block_ln_stats(t0, t1, red1, red2, lane, w, mean2, inv2);

#pragma unroll
    for (int gq = 0; gq < 2; gq++) {
        int j = gq ? j1 : j0;
        float4 v = gq ? t1 : t0;
        float4 gv = *(const float4*)&g2[j];
        float4 bv = *(const float4*)&b2[j];
        float4 o;
        o.x = (v.x - mean2) * inv2 * gv.x + bv.x;
        o.y = (v.y - mean2) * inv2 * gv.y + bv.y;
        o.z = (v.z - mean2) * inv2 * gv.z + bv.z;
        o.w = (v.w - mean2) * inv2 * gv.w + bv.w;
        *(float4*)&out[(size_t)r * H + j] = o;
        size_t ix = (size_t)r * H + j;
        split2(o.x, oh[ix + 0], ol[ix + 0]);
        split2(o.y, oh[ix + 1], ol[ix + 1]);
        split2(o.z, oh[ix + 2], ol[ix + 2]);
        split2(o.w, oh[ix + 3], ol[ix + 3]);
    }
}

// ---------------- batched cross-attn GEMV ------------------------------------
__global__ void gemv_ca(const float* __restrict__ xin, const float* __restrict__ Wt,
                        const float* __restrict__ bias, float* __restrict__ out, int mode)
{
    int n = blockIdx.x * 8 + (threadIdx.x >> 5);
    int lane = threadIdx.x & 31;
    int l = n >> 11, r = n & 2047;
    const float* w;
    const float* x;
    float b;
    if (mode == 0) {
        w = Wt + ((size_t)l * 3 * H + 2 * H + r) * H;
        x = xin;
        b = bias[(size_t)l * 3 * H + 2 * H + r];
    } else {
        w = Wt + ((size_t)l * H + r) * H;
        x = xin + (size_t)l * H;
        b = bias[(size_t)l * H + r];
    }
    float s = 0.f;
#pragma unroll 8
    for (int k = lane * 4; k < H; k += 128) {
        float4 a = *(const float4*)&x[k];
        float4 bw = *(const float4*)&w[k];
        s += a.x * bw.x + a.y * bw.y + a.z * bw.z + a.w * bw.w;
    }
#pragma unroll
    for (int o = 16; o; o >>= 1) s += __shfl_xor_sync(0xffffffffu, s, o);
    if (lane == 0) out[n] = s + b;
}

// ---------------- plain GEMV (size predictor layer 1) ------------------------
__global__ void gemv_kernel(
    const float* __restrict__ x, const float* __restrict__ W,
    const float* __restrict__ bias, float* __restrict__ out, int K, int act)
{
    int n = blockIdx.x * 8 + (threadIdx.x >> 5);
    int lane = threadIdx.x & 31;
    const float* w = W + (size_t)n * K;
    float s = 0.f;
#pragma unroll 8
    for (int k = lane * 4; k < K; k += 128) {
        float4 a = *(const float4*)&x[k];
        float4 b = *(const float4*)&w[k];
        s += a.x * b.x + a.y * b.y + a.z * b.z + a.w * b.w;
    }
#pragma unroll
    for (int o = 16; o; o >>= 1) s += __shfl_xor_sync(0xffffffffu, s, o);
    if (lane == 0) {
        s += bias[n];
        if (act) s = gelu_f(s);
        out[n] = s;
    }
}

// ---------------- self-attention (outputs bf16 split) ------------------------
__global__ void attn_kernel(const float* __restrict__ qkv,
                            __nv_bfloat16* __restrict__ oh,
                            __nv_bfloat16* __restrict__ ol)
{
    int h = blockIdx.x, bq = blockIdx.y;
    int tid = threadIdx.x;
    __shared__ float sc[8][32];

    int il = tid >> 5;
    int i = bq * 8 + il;
    int j = tid & 31;
    const float* q = qkv + (size_t)i * (3 * H) + h * DHD;
    const float* k = qkv + (size_t)j * (3 * H) + H + h * DHD;
    float s = 0.f;
#pragma unroll 8
    for (int d = 0; d < DHD; d += 4) {
        float4 a = *(const float4*)&q[d];
        float4 b = *(const float4*)&k[d];
        s += a.x * b.x + a.y * b.y + a.z * b.z + a.w * b.w;
    }
    s *= 0.0625f;
    float mx = s;
#pragma unroll
    for (int off = 16; off; off >>= 1) mx = fmaxf(mx, __shfl_xor_sync(0xffffffffu, mx, off));
    float p = expf(s - mx);
    float sum = p;
#pragma unroll
    for (int off = 16; off; off >>= 1) sum += __shfl_xor_sync(0xffffffffu, sum, off);
    sc[il][j] = p / sum;
    __syncthreads();

#pragma unroll
    for (int r = 0; r < 8; r++) {
        int u = tid + 256 * r;
        int ir = u >> 8;
        int d = u & 255;
        const float* vb = qkv + 2 * H + h * DHD + d;
        float acc = 0.f;
#pragma unroll
        for (int jj = 0; jj < 32; jj++)
            acc = fmaf(sc[ir][jj], vb[(size_t)jj * (3 * H)], acc);
        size_t ix = (size_t)(bq * 8 + ir) * H + h * DHD + d;
        split2(acc, oh[ix], ol[ix]);
    }
}

// ---------------- decoder input embedding (+ bf16 split) ---------------------
__global__ void embed_kernel(const int* __restrict__ tb,
                             const float* __restrict__ bemb,
                             const float* __restrict__ pemb,
                             float* __restrict__ x,
                             __nv_bfloat16* __restrict__ oh,
                             __nv_bfloat16* __restrict__ ol)
{
    int idx = blockIdx.x * 256 + threadIdx.x;
    int m = idx >> 11, j = idx & 2047;
    int tok = (m == 0) ? 256 : tb[m - 1];
    float v = bemb[(size_t)tok * H + j] + pemb[idx];
    x[idx] = v;
    split2(v, oh[idx], ol[idx]);
}

// ---------------- size predictor head 2 + softmax ----------------------------
__global__ void sp2_softmax(const float* __restrict__ hv, const float* __restrict__ W,
                            const float* __restrict__ bias, float* __restrict__ out)
{
    __shared__ float lg[33];
    int tid = threadIdx.x, w = tid >> 5, lane = tid & 31;
    for (int n = w; n < 33; n += 8) {
        const float* wr = W + (size_t)n * 1024;
        float s = 0.f;
#pragma unroll 8
        for (int k = lane * 4; k < 1024; k += 128) {
            float4 a = *(const float4*)&hv[k];
            float4 b = *(const float4*)&wr[k];
            s += a.x * b.x + a.y * b.y + a.z * b.z + a.w * b.w;
        }
#pragma unroll
        for (int o = 16; o; o >>= 1) s += __shfl_xor_sync(0xffffffffu, s, o);
        if (lane == 0) lg[n] = s + bias[n];
    }
    __syncthreads();
    if (tid == 0) {
        float mx = -1e30f;
        for (int n = 0; n < 33; n++) mx = fmaxf(mx, lg[n]);
        float sum = 0.f;
        for (int n = 0; n < 33; n++) { float e = expf(lg[n] - mx); lg[n] = e; sum += e; }
        float inv = 1.0f / sum;
        for (int n = 0; n < 33; n++) out[n] = lg[n] * inv;
    }
}

// =============================================================================
extern "C" void kernel_launch(void* const* d_in, const int* in_sizes, int n_in,
                              void* d_out, int out_size)
{
    const float* pe     = (const float*)d_in[0];
    const int*   tb     = (const int*)  d_in[1];
    const float* sp_w1  = (const float*)d_in[2];
    const float* sp_b1  = (const float*)d_in[3];
    const float* sp_w2  = (const float*)d_in[4];
    const float* sp_b2  = (const float*)d_in[5];
    const float* bemb   = (const float*)d_in[6];
    const float* pemb   = (const float*)d_in[7];
    const float* proj_w = (const float*)d_in[8];
    const float* proj_b = (const float*)d_in[9];
    const float* sa_in_w  = (const float*)d_in[10];
    const float* sa_in_b  = (const float*)d_in[11];
    const float* sa_out_w = (const float*)d_in[12];
    const float* sa_out_b = (const float*)d_in[13];
    const float* ca_in_w  = (const float*)d_in[14];
    const float* ca_in_b  = (const float*)d_in[15];
    const float* ca_out_w = (const float*)d_in[16];
    const float* ca_out_b = (const float*)d_in[17];
    const float* ff_w1 = (const float*)d_in[18];
    const float* ff_b1 = (const float*)d_in[19];
    const float* ff_w2 = (const float*)d_in[20];
    const float* ff_b2 = (const float*)d_in[21];
    const float* ln1_g = (const float*)d_in[22];
    const float* ln1_b = (const float*)d_in[23];
    const float* ln2_g = (const float*)d_in[24];
    const float* ln2_b = (const float*)d_in[25];
    const float* ln3_g = (const float*)d_in[26];
    const float* ln3_b = (const float*)d_in[27];

    float *x, *qkv, *part, *v1, *v2, *hbuf;
    __nv_bfloat16 *xh, *xl, *ah, *al, *gh, *gl;
    cudaGetSymbolAddress((void**)&x, g_x);
    cudaGetSymbolAddress((void**)&qkv, g_qkv);
    cudaGetSymbolAddress((void**)&part, g_part);
    cudaGetSymbolAddress((void**)&v1, g_v1);
    cudaGetSymbolAddress((void**)&v2, g_v2);
    cudaGetSymbolAddress((void**)&hbuf, g_h);
    cudaGetSymbolAddress((void**)&xh, g_xh);
    cudaGetSymbolAddress((void**)&xl, g_xl);
    cudaGetSymbolAddress((void**)&ah, g_ah);
    cudaGetSymbolAddress((void**)&al, g_al);
    cudaGetSymbolAddress((void**)&gh, g_gh);
    cudaGetSymbolAddress((void**)&gl, g_gl);

    // one-time side-stream/event infra (host objects, no device memory)
    static cudaStream_t s1 = nullptr;
    static cudaEvent_t evFork = nullptr, evJoin = nullptr;
    if (!s1) {
        cudaStreamCreateWithFlags(&s1, cudaStreamNonBlocking);
        cudaEventCreateWithFlags(&evFork, cudaEventDisableTiming);
        cudaEventCreateWithFlags(&evJoin, cudaEventDisableTiming);
    }

    float* out = (float*)d_out;

    // ---- fork: independent head + cross-attn vectors on side stream --------
    cudaEventRecord(evFork, 0);
    cudaStreamWaitEvent(s1, evFork, 0);
    gemv_kernel<<<1024 / 8, 256, 0, s1>>>(pe, sp_w1, sp_b1, hbuf, 2048, 1);
    sp2_softmax<<<1, 256, 0, s1>>>(hbuf, sp_w2, sp_b2, out);
    gemv_ca<<<(NLAYER * H) / 8, 256, 0, s1>>>(pe, ca_in_w, ca_in_b, v1, 0);
    gemv_ca<<<(NLAYER * H) / 8, 256, 0, s1>>>(v1, ca_out_w, ca_out_b, v2, 1);
    cudaEventRecord(evJoin, s1);

    // ---- main decoder chain (default stream) --------------------------------
    embed_kernel<<<(S * H) / 256, 256>>>(tb, bemb, pemb, x, xh, xl);

    for (int l = 0; l < 3; l++) {
        // --- self attention ---
        gemmW<<<dim3(96, 8), 256>>>(xh, xl, sa_in_w + (size_t)l * 3 * H * H,
                                    part, H, 256);
        combine_kernel<<<(32 * 6144) / 256, 256>>>(part, 8, 6144,
                                                   sa_in_b + (size_t)l * 3 * H, qkv);
        attn_kernel<<<dim3(8, 4), 256>>>(qkv, ah, al);
        gemmW<<<dim3(32, 16), 256>>>(ah, al, sa_out_w + (size_t)l * H * H,
                                     part, H, 128);

        if (l == 0) cudaStreamWaitEvent(0, evJoin, 0);  // v2 ready before LN2 use

        // --- fused LN1 + cross-attn(+v2) + LN2 ---
        ln_dual_kernel<<<32, 256>>>(part, 16, sa_out_b + (size_t)l * H, x,
                                    ln1_g + (size_t)l * H, ln1_b + (size_t)l * H,
                                    v2 + (size_t)l * H,
                                    ln2_g + (size_t)l * H, ln2_b + (size_t)l * H,
                                    x, xh, xl);

        // --- feed forward ---
        gemmW<<<dim3(128, 8), 256>>>(xh, xl, ff_w1 + (size_t)l * 4 * H * H,
                                     part, H, 256);
        combine_gelu_bf16<<<(32 * 8192) / 256, 256>>>(part, 8, 8192,
                                                      ff_b1 + (size_t)l * 4 * H, gh, gl);
        gemmW<<<dim3(32, 16), 256>>>(gh, gl, ff_w2 + (size_t)l * H * 4 * H,
                                     part, 4 * H, 512);
        ln_part_kernel<<<32, 256>>>(part, 16, ff_b2 + (size_t)l * H, x,
                                    ln3_g + (size_t)l * H, ln3_b + (size_t)l * H,
                                    x, xh, xl);
    }

    // byte logits
    gemmW<<<dim3(4, 16), 256>>>(xh, xl, proj_w, part, H, 128);
    combine_kernel<<<(32 * 256) / 256, 256>>>(part, 16, 256, proj_b, out + 33);
}

// round 17
// speedup vs baseline: 1.5872x; 1.0906x over previous
#include <cuda_runtime.h>
#include <cuda_bf16.h>
#include <math.h>
#include <stdint.h>

#define H 2048
#define S 32
#define NHEAD 8
#define DHD 256
#define NLAYER 3

// ---------------- scratch (device globals; no allocation allowed) ------------
__device__ float g_x[S * H];
__device__ float g_qkv[S * 3 * H];
__device__ float g_part[4194304];
__device__ float g_v1[NLAYER * H];
__device__ float g_v2[NLAYER * H];
__device__ float g_h[1024];
__device__ __nv_bfloat16 g_xh[S * H];
__device__ __nv_bfloat16 g_xl[S * H];
__device__ __nv_bfloat16 g_ah[S * H];
__device__ __nv_bfloat16 g_al[S * H];
__device__ __nv_bfloat16 g_gh[S * 4 * H];
__device__ __nv_bfloat16 g_gl[S * 4 * H];

__device__ __forceinline__ float gelu_f(float v) {
    return 0.5f * v * (1.0f + erff(v * 0.70710678118654752f));
}
__device__ __forceinline__ void split2(float x, __nv_bfloat16& h, __nv_bfloat16& l) {
    unsigned u = __float_as_uint(x);
    h = __ushort_as_bfloat16((unsigned short)(u >> 16));
    l = __float2bfloat16(x - __uint_as_float(u & 0xFFFF0000u));
}

// ======================= HMMA GEMM (R11 version — best passing) ==============
// Cp[32,N] slice = X[32,Kslice] @ W[N,Kslice]^T as D[64 wrow, 32 tok] per block.
// 128 threads / 4 warps. fp32 emulated by bf16 hi/lo split: hh+hl+lh passes.
// 2-deep register pipeline, single smem buffer.

#define WSTR 40   // padded row stride (bf16): 80B; 16B-aligned rows, 0-conflict

__device__ __forceinline__ uint32_t sptr(const void* p) {
    return (uint32_t)__cvta_generic_to_shared(p);
}
__device__ __forceinline__ void ldsm4(uint32_t* r, uint32_t a) {
    asm volatile("ldmatrix.sync.aligned.m8n8.x4.shared.b16 {%0,%1,%2,%3}, [%4];"
                 : "=r"(r[0]), "=r"(r[1]), "=r"(r[2]), "=r"(r[3]) : "r"(a));
}
__device__ __forceinline__ void mma16816(float* d, const uint32_t* a,
                                         uint32_t b0, uint32_t b1) {
    asm volatile(
        "mma.sync.aligned.m16n8k16.row.col.f32.bf16.bf16.f32 "
        "{%0,%1,%2,%3}, {%4,%5,%6,%7}, {%8,%9}, {%0,%1,%2,%3};"
        : "+f"(d[0]), "+f"(d[1]), "+f"(d[2]), "+f"(d[3])
        : "r"(a[0]), "r"(a[1]), "r"(a[2]), "r"(a[3]), "r"(b0), "r"(b1));
}

// stage one 32-k tile from registers into smem (W f32 -> bf16 hi/lo)
__device__ __forceinline__ void gm_stage(
    const float4* wreg, uint4 xh4, uint4 xl4,
    __nv_bfloat16* sWH, __nv_bfloat16* sWL,
    __nv_bfloat16* sXH, __nv_bfloat16* sXL,
    int wrow, int hf, int xrow, int xc)
{
#pragma unroll
    for (int i = 0; i < 4; i++) {
        float4 f = wreg[i];
        unsigned u0 = __float_as_uint(f.x), u1 = __float_as_uint(f.y);
        unsigned u2 = __float_as_uint(f.z), u3 = __float_as_uint(f.w);
        unsigned h01 = __byte_perm(u0, u1, 0x7632);
        unsigned h23 = __byte_perm(u2, u3, 0x7632);
        float l0 = f.x - __uint_as_float(u0 & 0xFFFF0000u);
        float l1 = f.y - __uint_as_float(u1 & 0xFFFF0000u);
        float l2 = f.z - __uint_as_float(u2 & 0xFFFF0000u);
        float l3 = f.w - __uint_as_float(u3 & 0xFFFF0000u);
        unsigned l01, l23;
        asm("cvt.rn.bf16x2.f32 %0, %1, %2;" : "=r"(l01) : "f"(l1), "f"(l0));
        asm("cvt.rn.bf16x2.f32 %0, %1, %2;" : "=r"(l23) : "f"(l3), "f"(l2));
        int e = wrow * WSTR + hf * 16 + i * 4;
        *(uint2*)&sWH[e] = make_uint2(h01, h23);
        *(uint2*)&sWL[e] = make_uint2(l01, l23);
    }
    int e = xrow * WSTR + xc;
    *(uint4*)&sXH[e] = xh4;
    *(uint4*)&sXL[e] = xl4;
}

// consume the staged tile: per warp 16 W-rows, 2 k-steps x (6 ldsm + 12 mma)
__device__ __forceinline__ void gm_compute(
    float acc[4][4],
    const __nv_bfloat16* sWH, const __nv_bfloat16* sWL,
    const __nv_bfloat16* sXH, const __nv_bfloat16* sXL,
    int wid, int lane)
{
    const int m0 = wid * 16;
#pragma unroll
    for (int s = 0; s < 2; s++) {
        uint32_t ah[4], al[4], b0h[4], b1h[4], b0l[4], b1l[4];
        {
            int arow = m0 + (lane & 15);
            int acol = s * 16 + ((lane >> 4) << 3);
            ldsm4(ah, sptr(&sWH[arow * WSTR + acol]));
            ldsm4(al, sptr(&sWL[arow * WSTR + acol]));
        }
        {
            int brow = ((lane >> 4) << 3) + (lane & 7);
            int bcol = s * 16 + (lane & 8);
            ldsm4(b0h, sptr(&sXH[brow * WSTR + bcol]));
            ldsm4(b1h, sptr(&sXH[(16 + brow) * WSTR + bcol]));
            ldsm4(b0l, sptr(&sXL[brow * WSTR + bcol]));
            ldsm4(b1l, sptr(&sXL[(16 + brow) * WSTR + bcol]));
        }
        // hh
        mma16816(acc[0], ah, b0h[0], b0h[1]);
        mma16816(acc[1], ah, b0h[2], b0h[3]);
        mma16816(acc[2], ah, b1h[0], b1h[1]);
        mma16816(acc[3], ah, b1h[2], b1h[3]);
        // hl
        mma16816(acc[0], ah, b0l[0], b0l[1]);
        mma16816(acc[1], ah, b0l[2], b0l[3]);
        mma16816(acc[2], ah, b1l[0], b1l[1]);
        mma16816(acc[3], ah, b1l[2], b1l[3]);
        // lh
        mma16816(acc[0], al, b0h[0], b0h[1]);
        mma16816(acc[1], al, b0h[2], b0h[3]);
        mma16816(acc[2], al, b1h[0], b1h[1]);
        mma16816(acc[3], al, b1h[2], b1h[3]);
    }
}

__global__ __launch_bounds__(128) void gemmM(
    const __nv_bfloat16* __restrict__ XHg, const __nv_bfloat16* __restrict__ XLg,
    const float* __restrict__ W, float* __restrict__ Cp, int K, int kchunk)
{
    __shared__ __align__(16) __nv_bfloat16 sWH[64 * WSTR];
    __shared__ __align__(16) __nv_bfloat16 sWL[64 * WSTR];
    __shared__ __align__(16) __nv_bfloat16 sXH[32 * WSTR];
    __shared__ __align__(16) __nv_bfloat16 sXL[32 * WSTR];

    const int N  = gridDim.x * 64;
    const int n0 = blockIdx.x * 64;
    const int k0 = blockIdx.y * kchunk;
    const int tid = threadIdx.x, wid = tid >> 5, lane = tid & 31;

    const int wrow = tid >> 1;          // W row 0..63
    const int hf   = tid & 1;           // k-half (16 floats)
    const int xrow = tid >> 2;          // X row 0..31
    const int xc   = (tid & 3) * 8;     // 8 bf16 (16B) per chunk
    const float* wp = W + (size_t)(n0 + wrow) * K + k0 + hf * 16;
    const __nv_bfloat16* xhp = XHg + (size_t)xrow * K + k0 + xc;
    const __nv_bfloat16* xlp = XLg + (size_t)xrow * K + k0 + xc;

    float acc[4][4];
#pragma unroll
    for (int i = 0; i < 4; i++)
#pragma unroll
        for (int j = 0; j < 4; j++) acc[i][j] = 0.f;

    float4 wregA[4], wregB[4];
    uint4 xhA, xlA, xhB, xlB;

    const int tiles = kchunk >> 5;   // always even (>= 4)

    // prologue: tiles 0 and 1 -> register sets A and B
#pragma unroll
    for (int i = 0; i < 4; i++) wregA[i] = *(const float4*)(wp + i * 4);
    xhA = *(const uint4*)(xhp);
    xlA = *(const uint4*)(xlp);
#pragma unroll
    for (int i = 0; i < 4; i++) wregB[i] = *(const float4*)(wp + 32 + i * 4);
    xhB = *(const uint4*)(xhp + 32);
    xlB = *(const uint4*)(xlp + 32);

    for (int t = 0; t < tiles; t += 2) {
        // ---- tile t (set A) ----
        gm_stage(wregA, xhA, xlA, sWH, sWL, sXH, sXL, wrow, hf, xrow, xc);
        __syncthreads();
        if (t + 2 < tiles) {
            int kt = (t + 2) * 32;
#pragma unroll
            for (int i = 0; i < 4; i++)
                wregA[i] = *(const float4*)(wp + kt + i * 4);
            xhA = *(const uint4*)(xhp + kt);
            xlA = *(const uint4*)(xlp + kt);
        }
        gm_compute(acc, sWH, sWL, sXH, sXL, wid, lane);
        __syncthreads();

        // ---- tile t+1 (set B) ----
        gm_stage(wregB, xhB, xlB, sWH, sWL, sXH, sXL, wrow, hf, xrow, xc);
        __syncthreads();
        if (t + 3 < tiles) {
            int kt = (t + 3) * 32;
#pragma unroll
            for (int i = 0; i < 4; i++)
                wregB[i] = *(const float4*)(wp + kt + i * 4);
            xhB = *(const uint4*)(xhp + kt);
            xlB = *(const uint4*)(xlp + kt);
        }
        gm_compute(acc, sWH, sWL, sXH, sXL, wid, lane);
        __syncthreads();
    }

    // ---- epilogue: D frags -> Cp[token][n0 + wrow] ----
    {
        const int m0 = wid * 16;
        int r = lane >> 2, c2 = (lane & 3) * 2;
        float* cp = Cp + (size_t)blockIdx.y * 32 * N + n0;
#pragma unroll
        for (int nt = 0; nt < 4; nt++) {
            int tok = nt * 8 + c2;
            cp[(size_t)tok * N + m0 + r]           = acc[nt][0];
            cp[(size_t)(tok + 1) * N + m0 + r]     = acc[nt][1];
            cp[(size_t)tok * N + m0 + r + 8]       = acc[nt][2];
            cp[(size_t)(tok + 1) * N + m0 + r + 8] = acc[nt][3];
        }
    }
}

// ---------------- split-K combine + bias (f32 out) ---------------------------
__global__ void combine_kernel(
    const float* __restrict__ Cp, int KS, int N,
    const float* __restrict__ bias, float* __restrict__ out)
{
    int idx = blockIdx.x * 256 + threadIdx.x;
    int total = 32 * N;
    if (idx >= total) return;
    float s = 0.f;
#pragma unroll 4
    for (int k = 0; k < KS; k++) s += Cp[(size_t)k * total + idx];
    int m = idx / N;
    s += bias[idx - m * N];
    out[idx] = s;
}

// ---------------- split-K combine + bias + gelu -> bf16 hi/lo ----------------
__global__ void combine_gelu_bf16(
    const float* __restrict__ Cp, int KS, int N,
    const float* __restrict__ bias,
    __nv_bfloat16* __restrict__ oh, __nv_bfloat16* __restrict__ ol)
{
    int idx = blockIdx.x * 256 + threadIdx.x;
    int total = 32 * N;
    if (idx >= total) return;
    float s = 0.f;
#pragma unroll 4
    for (int k = 0; k < KS; k++) s += Cp[(size_t)k * total + idx];
    int m = idx / N;
    s += bias[idx - m * N];
    s = gelu_f(s);
    split2(s, oh[idx], ol[idx]);
}

// ---- warp/block LN helper: mean + inv-std over 8 vals/thread ----------------
__device__ __forceinline__ void block_ln_stats(
    float4 s0, float4 s1, float* red1, float* red2,
    int lane, int w, float& mean, float& inv)
{
    float lsum = s0.x + s0.y + s0.z + s0.w + s1.x + s1.y + s1.z + s1.w;
#pragma unroll
    for (int o = 16; o; o >>= 1) lsum += __shfl_xor_sync(0xffffffffu, lsum, o);
    if (lane == 0) red1[w] = lsum;
    __syncthreads();
    mean = (red1[0] + red1[1] + red1[2] + red1[3] +
            red1[4] + red1[5] + red1[6] + red1[7]) * (1.0f / H);
    float lsq = 0.f, d;
    d = s0.x - mean; lsq += d * d;  d = s0.y - mean; lsq += d * d;
    d = s0.z - mean; lsq += d * d;  d = s0.w - mean; lsq += d * d;
    d = s1.x - mean; lsq += d * d;  d = s1.y - mean; lsq += d * d;
    d = s1.z - mean; lsq += d * d;  d = s1.w - mean; lsq += d * d;
#pragma unroll
    for (int o = 16; o; o >>= 1) lsq += __shfl_xor_sync(0xffffffffu, lsq, o);
    if (lane == 0) red2[w] = lsq;
    __syncthreads();
    float var = (red2[0] + red2[1] + red2[2] + red2[3] +
                 red2[4] + red2[5] + red2[6] + red2[7]) * (1.0f / H);
    inv = rsqrtf(var + 1e-5f);
}

// ------- fused split-K combine + bias + residual + LayerNorm (+bf16) ---------
__global__ void ln_part_kernel(
    const float* __restrict__ Cp, int KS,
    const float* __restrict__ bias, const float* __restrict__ resid,
    const float* __restrict__ gg, const float* __restrict__ bb,
    float* __restrict__ out,
    __nv_bfloat16* __restrict__ oh, __nv_bfloat16* __restrict__ ol)
{
    __shared__ float red1[8];
    __shared__ float red2[8];
    int r = blockIdx.x, tid = threadIdx.x;
    int lane = tid & 31, w = tid >> 5;
    int j0 = tid * 4, j1 = tid * 4 + 1024;

    float4 s0 = make_float4(0.f, 0.f, 0.f, 0.f);
    float4 s1 = make_float4(0.f, 0.f, 0.f, 0.f);
#pragma unroll 4
    for (int k = 0; k < KS; k++) {
        const float* p = Cp + ((size_t)k * 32 + r) * H;
        float4 a = *(const float4*)&p[j0];
        float4 b = *(const float4*)&p[j1];
        s0.x += a.x; s0.y += a.y; s0.z += a.z; s0.w += a.w;
        s1.x += b.x; s1.y += b.y; s1.z += b.z; s1.w += b.w;
    }
    {
        float4 a = *(const float4*)&bias[j0];
        float4 b = *(const float4*)&bias[j1];
        s0.x += a.x; s0.y += a.y; s0.z += a.z; s0.w += a.w;
        s1.x += b.x; s1.y += b.y; s1.z += b.z; s1.w += b.w;
        a = *(const float4*)&resid[(size_t)r * H + j0];
        b = *(const float4*)&resid[(size_t)r * H + j1];
        s0.x += a.x; s0.y += a.y; s0.z += a.z; s0.w += a.w;
        s1.x += b.x; s1.y += b.y; s1.z += b.z; s1.w += b.w;
    }

    float mean, inv;
    block_ln_stats(s0, s1, red1, red2, lane, w, mean, inv);

#pragma unroll
    for (int g2 = 0; g2 < 2; g2++) {
        int j = g2 ? j1 : j0;
        float4 v = g2 ? s1 : s0;
        float4 gv = *(const float4*)&gg[j];
        float4 bv = *(const float4*)&bb[j];
        float4 o;
        o.x = (v.x - mean) * inv * gv.x + bv.x;
        o.y = (v.y - mean) * inv * gv.y + bv.y;
        o.z = (v.z - mean) * inv * gv.z + bv.z;
        o.w = (v.w - mean) * inv * gv.w + bv.w;
        *(float4*)&out[(size_t)r * H + j] = o;
        if (oh) {
            size_t ix = (size_t)r * H + j;
            split2(o.x, oh[ix + 0], ol[ix + 0]);
            split2(o.y, oh[ix + 1], ol[ix + 1]);
            split2(o.z, oh[ix + 2], ol[ix + 2]);
            split2(o.w, oh[ix + 3], ol[ix + 3]);
        }
    }
}

// -- fused: combine+bias+resid -> LN1 -> +v2 -> LN2 -> out (+bf16 split) ------
__global__ void ln_dual_kernel(
    const float* __restrict__ Cp, int KS,
    const float* __restrict__ bias, const float* __restrict__ resid,
    const float* __restrict__ g1, const float* __restrict__ b1,
    const float* __restrict__ v2,
    const float* __restrict__ g2, const float* __restrict__ b2,
    float* __restrict__ out,
    __nv_bfloat16* __restrict__ oh, __nv_bfloat16* __restrict__ ol)
{
    __shared__ float red1[8];
    __shared__ float red2[8];
    int r = blockIdx.x, tid = threadIdx.x;
    int lane = tid & 31, w = tid >> 5;
    int j0 = tid * 4, j1 = tid * 4 + 1024;

    float4 s0 = make_float4(0.f, 0.f, 0.f, 0.f);
    float4 s1 = make_float4(0.f, 0.f, 0.f, 0.f);
#pragma unroll 4
    for (int k = 0; k < KS; k++) {
        const float* p = Cp + ((size_t)k * 32 + r) * H;
        float4 a = *(const float4*)&p[j0];
        float4 b = *(const float4*)&p[j1];
        s0.x += a.x; s0.y += a.y; s0.z += a.z; s0.w += a.w;
        s1.x += b.x; s1.y += b.y; s1.z += b.z; s1.w += b.w;
    }
    {
        float4 a = *(const float4*)&bias[j0];
        float4 b = *(const float4*)&bias[j1];
        s0.x += a.x; s0.y += a.y; s0.z += a.z; s0.w += a.w;
        s1.x += b.x; s1.y += b.y; s1.z += b.z; s1.w += b.w;
        a = *(const float4*)&resid[(size_t)r * H + j0];
        b = *(const float4*)&resid[(size_t)r * H + j1];
        s0.x += a.x; s0.y += a.y; s0.z += a.z; s0.w += a.w;
        s1.x += b.x; s1.y += b.y; s1.z += b.z; s1.w += b.w;
    }

    float mean, inv;
    block_ln_stats(s0, s1, red1, red2, lane, w, mean, inv);

    float4 t0, t1;
    {
        float4 gv = *(const float4*)&g1[j0];
        float4 bv = *(const float4*)&b1[j0];
        float4 vv = *(const float4*)&v2[j0];
        t0.x = (s0.x - mean) * inv * gv.x + bv.x + vv.x;
        t0.y = (s0.y - mean) * inv * gv.y + bv.y + vv.y;
        t0.z = (s0.z - mean) * inv * gv.z + bv.z + vv.z;
        t0.w = (s0.w - mean) * inv * gv.w + bv.w + vv.w;
        gv = *(const float4*)&g1[j1];
        bv = *(const float4*)&b1[j1];
        vv = *(const float4*)&v2[j1];
        t1.x = (s1.x - mean) * inv * gv.x + bv.x + vv.x;
        t1.y = (s1.y - mean) * inv * gv.y + bv.y + vv.y;
        t1.z = (s1.z - mean) * inv * gv.z + bv.z + vv.z;
        t1.w = (s1.w - mean) * inv * gv.w + bv.w + vv.w;
    }
    __syncthreads();

    float mean2, inv2;
    block_ln_stats(t0, t1, red1, red2, lane, w, mean2, inv2);

#pragma unroll
    for (int gq = 0; gq < 2; gq++) {
        int j = gq ? j1 : j0;
        float4 v = gq ? t1 : t0;
        float4 gv = *(const float4*)&g2[j];
        float4 bv = *(const float4*)&b2[j];
        float4 o;
        o.x = (v.x - mean2) * inv2 * gv.x + bv.x;
        o.y = (v.y - mean2) * inv2 * gv.y + bv.y;
        o.z = (v.z - mean2) * inv2 * gv.z + bv.z;
        o.w = (v.w - mean2) * inv2 * gv.w + bv.w;
        *(float4*)&out[(size_t)r * H + j] = o;
        size_t ix = (size_t)r * H + j;
        split2(o.x, oh[ix + 0], ol[ix + 0]);
        split2(o.y, oh[ix + 1], ol[ix + 1]);
        split2(o.z, oh[ix + 2], ol[ix + 2]);
        split2(o.w, oh[ix + 3], ol[ix + 3]);
    }
}

// ---------------- batched cross-attn GEMV ------------------------------------
__global__ void gemv_ca(const float* __restrict__ xin, const float* __restrict__ Wt,
                        const float* __restrict__ bias, float* __restrict__ out, int mode)
{
    int n = blockIdx.x * 8 + (threadIdx.x >> 5);
    int lane = threadIdx.x & 31;
    int l = n >> 11, r = n & 2047;
    const float* w;
    const float* x;
    float b;
    if (mode == 0) {
        w = Wt + ((size_t)l * 3 * H + 2 * H + r) * H;
        x = xin;
        b = bias[(size_t)l * 3 * H + 2 * H + r];
    } else {
        w = Wt + ((size_t)l * H + r) * H;
        x = xin + (size_t)l * H;
        b = bias[(size_t)l * H + r];
    }
    float s = 0.f;
#pragma unroll 8
    for (int k = lane * 4; k < H; k += 128) {
        float4 a = *(const float4*)&x[k];
        float4 bw = *(const float4*)&w[k];
        s += a.x * bw.x + a.y * bw.y + a.z * bw.z + a.w * bw.w;
    }
#pragma unroll
    for (int o = 16; o; o >>= 1) s += __shfl_xor_sync(0xffffffffu, s, o);
    if (lane == 0) out[n] = s + b;
}

// ---------------- plain GEMV (size predictor layer 1) ------------------------
__global__ void gemv_kernel(
    const float* __restrict__ x, const float* __restrict__ W,
    const float* __restrict__ bias, float* __restrict__ out, int K, int act)
{
    int n = blockIdx.x * 8 + (threadIdx.x >> 5);
    int lane = threadIdx.x & 31;
    const float* w = W + (size_t)n * K;
    float s = 0.f;
#pragma unroll 8
    for (int k = lane * 4; k < K; k += 128) {
        float4 a = *(const float4*)&x[k];
        float4 b = *(const float4*)&w[k];
        s += a.x * b.x + a.y * b.y + a.z * b.z + a.w * b.w;
    }
#pragma unroll
    for (int o = 16; o; o >>= 1) s += __shfl_xor_sync(0xffffffffu, s, o);
    if (lane == 0) {
        s += bias[n];
        if (act) s = gelu_f(s);
        out[n] = s;
    }
}

// ---------------- self-attention (outputs bf16 split) ------------------------
__global__ void attn_kernel(const float* __restrict__ qkv,
                            __nv_bfloat16* __restrict__ oh,
                            __nv_bfloat16* __restrict__ ol)
{
    int h = blockIdx.x, bq = blockIdx.y;
    int tid = threadIdx.x;
    __shared__ float sc[8][32];

    int il = tid >> 5;
    int i = bq * 8 + il;
    int j = tid & 31;
    const float* q = qkv + (size_t)i * (3 * H) + h * DHD;
    const float* k = qkv + (size_t)j * (3 * H) + H + h * DHD;
    float s = 0.f;
#pragma unroll 8
    for (int d = 0; d < DHD; d += 4) {
        float4 a = *(const float4*)&q[d];
        float4 b = *(const float4*)&k[d];
        s += a.x * b.x + a.y * b.y + a.z * b.z + a.w * b.w;
    }
    s *= 0.0625f;
    float mx = s;
#pragma unroll
    for (int off = 16; off; off >>= 1) mx = fmaxf(mx, __shfl_xor_sync(0xffffffffu, mx, off));
    float p = expf(s - mx);
    float sum = p;
#pragma unroll
    for (int off = 16; off; off >>= 1) sum += __shfl_xor_sync(0xffffffffu, sum, off);
    sc[il][j] = p / sum;
    __syncthreads();

#pragma unroll
    for (int r = 0; r < 8; r++) {
        int u = tid + 256 * r;
        int ir = u >> 8;
        int d = u & 255;
        const float* vb = qkv + 2 * H + h * DHD + d;
        float acc = 0.f;
#pragma unroll
        for (int jj = 0; jj < 32; jj++)
            acc = fmaf(sc[ir][jj], vb[(size_t)jj * (3 * H)], acc);
        size_t ix = (size_t)(bq * 8 + ir) * H + h * DHD + d;
        split2(acc, oh[ix], ol[ix]);
    }
}

// ---------------- decoder input embedding (+ bf16 split) ---------------------
__global__ void embed_kernel(const int* __restrict__ tb,
                             const float* __restrict__ bemb,
                             const float* __restrict__ pemb,
                             float* __restrict__ x,
                             __nv_bfloat16* __restrict__ oh,
                             __nv_bfloat16* __restrict__ ol)
{
    int idx = blockIdx.x * 256 + threadIdx.x;
    int m = idx >> 11, j = idx & 2047;
    int tok = (m == 0) ? 256 : tb[m - 1];
    float v = bemb[(size_t)tok * H + j] + pemb[idx];
    x[idx] = v;
    split2(v, oh[idx], ol[idx]);
}

// ---------------- size predictor head 2 + softmax ----------------------------
__global__ void sp2_softmax(const float* __restrict__ hv, const float* __restrict__ W,
                            const float* __restrict__ bias, float* __restrict__ out)
{
    __shared__ float lg[33];
    int tid = threadIdx.x, w = tid >> 5, lane = tid & 31;
    for (int n = w; n < 33; n += 8) {
        const float* wr = W + (size_t)n * 1024;
        float s = 0.f;
#pragma unroll 8
        for (int k = lane * 4; k < 1024; k += 128) {
            float4 a = *(const float4*)&hv[k];
            float4 b = *(const float4*)&wr[k];
            s += a.x * b.x + a.y * b.y + a.z * b.z + a.w * b.w;
        }
#pragma unroll
        for (int o = 16; o; o >>= 1) s += __shfl_xor_sync(0xffffffffu, s, o);
        if (lane == 0) lg[n] = s + bias[n];
    }
    __syncthreads();
    if (tid == 0) {
        float mx = -1e30f;
        for (int n = 0; n < 33; n++) mx = fmaxf(mx, lg[n]);
        float sum = 0.f;
        for (int n = 0; n < 33; n++) { float e = expf(lg[n] - mx); lg[n] = e; sum += e; }
        float inv = 1.0f / sum;
        for (int n = 0; n < 33; n++) out[n] = lg[n] * inv;
    }
}

// =============================================================================
extern "C" void kernel_launch(void* const* d_in, const int* in_sizes, int n_in,
                              void* d_out, int out_size)
{
    const float* pe     = (const float*)d_in[0];
    const int*   tb     = (const int*)  d_in[1];
    const float* sp_w1  = (const float*)d_in[2];
    const float* sp_b1  = (const float*)d_in[3];
    const float* sp_w2  = (const float*)d_in[4];
    const float* sp_b2  = (const float*)d_in[5];
    const float* bemb   = (const float*)d_in[6];
    const float* pemb   = (const float*)d_in[7];
    const float* proj_w = (const float*)d_in[8];
    const float* proj_b = (const float*)d_in[9];
    const float* sa_in_w  = (const float*)d_in[10];
    const float* sa_in_b  = (const float*)d_in[11];
    const float* sa_out_w = (const float*)d_in[12];
    const float* sa_out_b = (const float*)d_in[13];
    const float* ca_in_w  = (const float*)d_in[14];
    const float* ca_in_b  = (const float*)d_in[15];
    const float* ca_out_w = (const float*)d_in[16];
    const float* ca_out_b = (const float*)d_in[17];
    const float* ff_w1 = (const float*)d_in[18];
    const float* ff_b1 = (const float*)d_in[19];
    const float* ff_w2 = (const float*)d_in[20];
    const float* ff_b2 = (const float*)d_in[21];
    const float* ln1_g = (const float*)d_in[22];
    const float* ln1_b = (const float*)d_in[23];
    const float* ln2_g = (const float*)d_in[24];
    const float* ln2_b = (const float*)d_in[25];
    const float* ln3_g = (const float*)d_in[26];
    const float* ln3_b = (const float*)d_in[27];

    float *x, *qkv, *part, *v1, *v2, *hbuf;
    __nv_bfloat16 *xh, *xl, *ah, *al, *gh, *gl;
    cudaGetSymbolAddress((void**)&x, g_x);
    cudaGetSymbolAddress((void**)&qkv, g_qkv);
    cudaGetSymbolAddress((void**)&part, g_part);
    cudaGetSymbolAddress((void**)&v1, g_v1);
    cudaGetSymbolAddress((void**)&v2, g_v2);
    cudaGetSymbolAddress((void**)&hbuf, g_h);
    cudaGetSymbolAddress((void**)&xh, g_xh);
    cudaGetSymbolAddress((void**)&xl, g_xl);
    cudaGetSymbolAddress((void**)&ah, g_ah);
    cudaGetSymbolAddress((void**)&al, g_al);
    cudaGetSymbolAddress((void**)&gh, g_gh);
    cudaGetSymbolAddress((void**)&gl, g_gl);

    // one-time side-stream/event infra (host objects, no device memory)
    static cudaStream_t s1 = nullptr;
    static cudaEvent_t evFork = nullptr, evJoin = nullptr;
    if (!s1) {
        cudaStreamCreateWithFlags(&s1, cudaStreamNonBlocking);
        cudaEventCreateWithFlags(&evFork, cudaEventDisableTiming);
        cudaEventCreateWithFlags(&evJoin, cudaEventDisableTiming);
    }

    float* out = (float*)d_out;

    // ---- fork: independent head + cross-attn vectors on side stream --------
    cudaEventRecord(evFork, 0);
    cudaStreamWaitEvent(s1, evFork, 0);
    gemv_kernel<<<1024 / 8, 256, 0, s1>>>(pe, sp_w1, sp_b1, hbuf, 2048, 1);
    sp2_softmax<<<1, 256, 0, s1>>>(hbuf, sp_w2, sp_b2, out);
    gemv_ca<<<(NLAYER * H) / 8, 256, 0, s1>>>(pe, ca_in_w, ca_in_b, v1, 0);
    gemv_ca<<<(NLAYER * H) / 8, 256, 0, s1>>>(v1, ca_out_w, ca_out_b, v2, 1);
    cudaEventRecord(evJoin, s1);

    // ---- main decoder chain (default stream) --------------------------------
    embed_kernel<<<(S * H) / 256, 256>>>(tb, bemb, pemb, x, xh, xl);

    for (int l = 0; l < 3; l++) {
        // --- self attention ---
        gemmM<<<dim3(96, 4), 128>>>(xh, xl, sa_in_w + (size_t)l * 3 * H * H,
                                    part, H, 512);
        combine_kernel<<<(32 * 6144) / 256, 256>>>(part, 4, 6144,
                                                   sa_in_b + (size_t)l * 3 * H, qkv);
        attn_kernel<<<dim3(8, 4), 256>>>(qkv, ah, al);
        gemmM<<<dim3(32, 16), 128>>>(ah, al, sa_out_w + (size_t)l * H * H,
                                     part, H, 128);

        if (l == 0) cudaStreamWaitEvent(0, evJoin, 0);  // v2 ready before LN2 use

        // --- fused LN1 + cross-attn(+v2) + LN2 ---
        ln_dual_kernel<<<32, 256>>>(part, 16, sa_out_b + (size_t)l * H, x,
                                    ln1_g + (size_t)l * H, ln1_b + (size_t)l * H,
                                    v2 + (size_t)l * H,
                                    ln2_g + (size_t)l * H, ln2_b + (size_t)l * H,
                                    x, xh, xl);

        // --- feed forward ---
        gemmM<<<dim3(128, 4), 128>>>(xh, xl, ff_w1 + (size_t)l * 4 * H * H,
                                     part, H, 512);
        combine_gelu_bf16<<<(32 * 8192) / 256, 256>>>(part, 4, 8192,
                                                      ff_b1 + (size_t)l * 4 * H, gh, gl);
        gemmM<<<dim3(32, 16), 128>>>(gh, gl, ff_w2 + (size_t)l * H * 4 * H,
                                     part, 4 * H, 512);
        ln_part_kernel<<<32, 256>>>(part, 16, ff_b2 + (size_t)l * H, x,
                                    ln3_g + (size_t)l * H, ln3_b + (size_t)l * H,
                                    x, xh, xl);
    }

    // byte logits
    gemmM<<<dim3(4, 16), 128>>>(xh, xl, proj_w, part, H, 128);
    combine_kernel<<<(32 * 256) / 256, 256>>>(part, 16, 256, proj_b, out + 33);
}